// round 4
// baseline (speedup 1.0000x reference)
#include <cuda_runtime.h>
#include <math.h>

// MLP: [N,4] -> tanh(@W1[4,128]) -> tanh(@W2[128,128]) -> tanh(@W3[128,128]) -> @W4[128,2]
// N = 524288. fp32 FFMA baseline, FMA-pipe-bound by design.
//
// Layout: one CTA = 128 points ("TM"). 256 threads: thread t -> neuron j = t&127,
// m-half = t>>7 (64 points each). W2/W3 column j lives in 128 registers per thread
// (coalesced loads, fully unrolled k loop). Activations ping-pong in dynamic smem
// with 132-float row pitch (16B-aligned float4 rows, broadcast reads).

#define TM  128
#define HID 128
#define PITCH 132   // 128 + 4 pad, multiple of 4 for LDS.128 alignment

__device__ __forceinline__ float my_tanh(float v) {
    // tanh(v) = sign(v) * (1 - 2/(e^{2|v|}+1)); clamp so __expf never overflows.
    float av = fminf(fabsf(v), 15.0f);
    float e  = __expf(2.0f * av);
    float r  = 1.0f - __fdividef(2.0f, e + 1.0f);
    return copysignf(r, v);
}

// One hidden layer: hout[m][j] = tanh(b[j] + sum_k hin[m][k] * W[k*128+j])
// Thread owns neuron j and 64 m's starting at m0. W column cached in registers.
__device__ __forceinline__ void layer_ffma(const float* __restrict__ hin,
                                           float* __restrict__ hout,
                                           const float* __restrict__ W,
                                           const float* __restrict__ b,
                                           int j, int m0) {
    float w[HID];
#pragma unroll
    for (int k = 0; k < HID; ++k) w[k] = W[k * HID + j];   // coalesced across j
    float bb = b[j];

#pragma unroll 1
    for (int mg = 0; mg < 64; mg += 8) {
        float acc[8];
#pragma unroll
        for (int i = 0; i < 8; ++i) acc[i] = bb;
        const float* hp = hin + (size_t)(m0 + mg) * PITCH;
#pragma unroll
        for (int k = 0; k < HID; k += 4) {        // fully unrolled: w[] stays in regs
#pragma unroll
            for (int i = 0; i < 8; ++i) {
                float4 h4 = *(const float4*)(hp + (size_t)i * PITCH + k); // broadcast LDS.128
                acc[i] = fmaf(h4.x, w[k + 0], acc[i]);
                acc[i] = fmaf(h4.y, w[k + 1], acc[i]);
                acc[i] = fmaf(h4.z, w[k + 2], acc[i]);
                acc[i] = fmaf(h4.w, w[k + 3], acc[i]);
            }
        }
#pragma unroll
        for (int i = 0; i < 8; ++i)
            hout[(size_t)(m0 + mg + i) * PITCH + j] = my_tanh(acc[i]);
    }
}

__global__ __launch_bounds__(256)
void mlp_kernel(const float* __restrict__ x,  const float* __restrict__ y,
                const float* __restrict__ c1, const float* __restrict__ c2,
                const float* __restrict__ W1, const float* __restrict__ b1,
                const float* __restrict__ W2, const float* __restrict__ b2,
                const float* __restrict__ W3, const float* __restrict__ b3,
                const float* __restrict__ W4, const float* __restrict__ b4,
                float* __restrict__ out, int npts) {
    extern __shared__ float sm[];
    float* sh1 = sm;                       // TM * PITCH
    float* sh2 = sm + TM * PITCH;          // TM * PITCH
    float* sin4 = sm + 2 * TM * PITCH;     // 4 * TM
    float* sw4  = sin4 + 4 * TM;           // 256
    float* sb4  = sw4 + 256;               // 2

    const int t    = threadIdx.x;
    const int j    = t & 127;
    const int half = t >> 7;
    const int base = blockIdx.x * TM;
    const int rem  = npts - base;
    const int mcnt = rem < TM ? rem : TM;

    // Stage inputs (guarded; zero-fill tail so junk never reaches expf unclamped paths)
    for (int i = t; i < TM; i += 256) {
        bool ok = (i < mcnt);
        sin4[0 * TM + i] = ok ? x [base + i] : 0.0f;
        sin4[1 * TM + i] = ok ? y [base + i] : 0.0f;
        sin4[2 * TM + i] = ok ? c1[base + i] : 0.0f;
        sin4[3 * TM + i] = ok ? c2[base + i] : 0.0f;
    }
    if (t < 256) sw4[t] = W4[t];
    if (t < 2)   sb4[t] = b4[t];

    // Layer-1 weights for neuron j
    const float w10 = W1[0 * HID + j], w11 = W1[1 * HID + j];
    const float w12 = W1[2 * HID + j], w13 = W1[3 * HID + j];
    const float bb1 = b1[j];
    __syncthreads();

    // Layer 1
    const int m0 = half * (TM / 2);
#pragma unroll 4
    for (int m = m0; m < m0 + TM / 2; ++m) {
        float h = bb1;
        h = fmaf(sin4[0 * TM + m], w10, h);
        h = fmaf(sin4[1 * TM + m], w11, h);
        h = fmaf(sin4[2 * TM + m], w12, h);
        h = fmaf(sin4[3 * TM + m], w13, h);
        sh1[(size_t)m * PITCH + j] = my_tanh(h);
    }
    __syncthreads();

    // Layers 2 & 3 (register-resident weight columns)
    layer_ffma(sh1, sh2, W2, b2, j, m0);
    __syncthreads();
    layer_ffma(sh2, sh1, W3, b3, j, m0);
    __syncthreads();

    // Layer 4: out[m][c] = b4[c] + sum_j h3[m][j] * W4[j*2+c]
    for (int idx = t; idx < TM * 2; idx += 256) {
        int m = idx >> 1, c = idx & 1;
        if (m >= mcnt) break;
        float acc = sb4[c];
        const float* hrow = sh1 + (size_t)m * PITCH;
#pragma unroll 8
        for (int k = 0; k < HID; ++k)
            acc = fmaf(hrow[k], sw4[k * 2 + c], acc);
        out[(size_t)(base + m) * 2 + c] = acc;
    }
}

extern "C" void kernel_launch(void* const* d_in, const int* in_sizes, int n_in,
                              void* d_out, int out_size) {
    const float* x  = (const float*)d_in[0];
    const float* y  = (const float*)d_in[1];
    const float* c1 = (const float*)d_in[2];
    const float* c2 = (const float*)d_in[3];
    const float* W1 = (const float*)d_in[4];
    const float* b1 = (const float*)d_in[5];
    const float* W2 = (const float*)d_in[6];
    const float* b2 = (const float*)d_in[7];
    const float* W3 = (const float*)d_in[8];
    const float* b3 = (const float*)d_in[9];
    const float* W4 = (const float*)d_in[10];
    const float* b4 = (const float*)d_in[11];
    float* out = (float*)d_out;

    const int npts = in_sizes[0];
    const int grid = (npts + TM - 1) / TM;
    const size_t smem = (size_t)(2 * TM * PITCH + 4 * TM + 256 + 2) * sizeof(float);

    cudaFuncSetAttribute(mlp_kernel, cudaFuncAttributeMaxDynamicSharedMemorySize, (int)smem);

    mlp_kernel<<<grid, 256, smem>>>(x, y, c1, c2, W1, b1, W2, b2, W3, b3, W4, b4,
                                    out, npts);
}

// round 5
// speedup vs baseline: 1.4929x; 1.4929x over previous
#include <cuda_runtime.h>
#include <math.h>

// MLP: [N,4] -> tanh(@W1[4,128]) -> tanh(@W2[128,128]) -> tanh(@W3[128,128]) -> @W4[128,2]
// N = 524288.  R4: 8x8 register tiling + packed fp32x2 FFMA (fma.rn.f32x2).
//
// CTA = 128 points x 128 neurons, 256 threads, thread tile = 8m x 8j.
// Activations ping-pong in smem as [row][col] pitch-132 buffers:
//   L1 out / L2 out : [k][m]   (k = neuron of producing layer)
//   L3 out          : [m][j]   (so layer-4 reads contiguous rows)
// Current layer weights (64KB) are staged into smem before each big layer.

#define TM   128
#define HID  128
#define P    132   // pitch in floats (16B-aligned rows)
typedef unsigned long long u64;

__device__ __forceinline__ u64 pack_dup(float x) {
    u64 r; asm("mov.b64 %0, {%1, %1};" : "=l"(r) : "f"(x)); return r;
}
__device__ __forceinline__ void unpack2(u64 v, float &lo, float &hi) {
    asm("mov.b64 {%0, %1}, %2;" : "=f"(lo), "=f"(hi) : "l"(v));
}
// d.lo += a.lo*b.lo ; d.hi += a.hi*b.hi   (packed fp32 FMA, sm_100+)
__device__ __forceinline__ void ffma2(u64 &d, u64 a, u64 b) {
    asm("fma.rn.f32x2 %0, %1, %2, %0;" : "+l"(d) : "l"(a), "l"(b));
}

__device__ __forceinline__ float my_tanh(float v) {
    float av = fminf(fabsf(v), 15.0f);
    float e  = __expf(2.0f * av);
    float r  = 1.0f - __fdividef(2.0f, e + 1.0f);
    return copysignf(r, v);
}

// One 128x128x128 layer: out = tanh(in^T W + b), thread tile 8m x 8j.
// acc pairs are over m (packed from u64 loads); weights are dup-packed.
template<bool ROW_IS_M>
__device__ __forceinline__ void gemm_layer(const float* __restrict__ aIn,
                                           float* __restrict__ aOut,
                                           const float* __restrict__ sWp,
                                           const float* __restrict__ bias,
                                           int m0, int j0) {
    u64 acc[8][4];
#pragma unroll
    for (int jj = 0; jj < 8; ++jj) {
        u64 bb = pack_dup(bias[j0 + jj]);
#pragma unroll
        for (int mp = 0; mp < 4; ++mp) acc[jj][mp] = bb;
    }

#pragma unroll 4
    for (int k = 0; k < HID; ++k) {
        const float* ar = aIn + k * P + m0;
        ulonglong2 aA = *(const ulonglong2*)(ar);       // pairs (m0,m0+1),(m0+2,m0+3)
        ulonglong2 aB = *(const ulonglong2*)(ar + 4);   // pairs (m0+4..7)
        const float* wr = sWp + (k << 7) + j0;
        float4 w0 = *(const float4*)(wr);
        float4 w1 = *(const float4*)(wr + 4);

        u64 av[4] = { aA.x, aA.y, aB.x, aB.y };
        u64 wd[8];
        wd[0] = pack_dup(w0.x); wd[1] = pack_dup(w0.y);
        wd[2] = pack_dup(w0.z); wd[3] = pack_dup(w0.w);
        wd[4] = pack_dup(w1.x); wd[5] = pack_dup(w1.y);
        wd[6] = pack_dup(w1.z); wd[7] = pack_dup(w1.w);

#pragma unroll
        for (int jj = 0; jj < 8; ++jj)
#pragma unroll
            for (int mp = 0; mp < 4; ++mp)
                ffma2(acc[jj][mp], av[mp], wd[jj]);
    }

    if (!ROW_IS_M) {
        // store as [j][m]
#pragma unroll
        for (int jj = 0; jj < 8; ++jj) {
            float t[8];
#pragma unroll
            for (int mp = 0; mp < 4; ++mp) {
                float lo, hi; unpack2(acc[jj][mp], lo, hi);
                t[2 * mp]     = my_tanh(lo);
                t[2 * mp + 1] = my_tanh(hi);
            }
            float* o = aOut + (j0 + jj) * P + m0;
            *(float4*)(o)     = make_float4(t[0], t[1], t[2], t[3]);
            *(float4*)(o + 4) = make_float4(t[4], t[5], t[6], t[7]);
        }
    } else {
        // store as [m][j]
#pragma unroll
        for (int mp = 0; mp < 4; ++mp) {
            float tl[8], th[8];
#pragma unroll
            for (int jj = 0; jj < 8; ++jj) {
                float lo, hi; unpack2(acc[jj][mp], lo, hi);
                tl[jj] = my_tanh(lo);
                th[jj] = my_tanh(hi);
            }
            float* o0 = aOut + (m0 + 2 * mp) * P + j0;
            *(float4*)(o0)     = make_float4(tl[0], tl[1], tl[2], tl[3]);
            *(float4*)(o0 + 4) = make_float4(tl[4], tl[5], tl[6], tl[7]);
            float* o1 = aOut + (m0 + 2 * mp + 1) * P + j0;
            *(float4*)(o1)     = make_float4(th[0], th[1], th[2], th[3]);
            *(float4*)(o1 + 4) = make_float4(th[4], th[5], th[6], th[7]);
        }
    }
}

__global__ __launch_bounds__(256)
void mlp_kernel(const float* __restrict__ x,  const float* __restrict__ y,
                const float* __restrict__ c1, const float* __restrict__ c2,
                const float* __restrict__ W1, const float* __restrict__ b1,
                const float* __restrict__ W2, const float* __restrict__ b2,
                const float* __restrict__ W3, const float* __restrict__ b3,
                const float* __restrict__ W4, const float* __restrict__ b4,
                float* __restrict__ out, int npts) {
    extern __shared__ float sm[];
    float* actA = sm;                          // 128*P
    float* actB = actA + HID * P;              // 128*P
    float* sW   = actB + HID * P;              // 128*128
    float* sIn  = sW   + HID * HID;            // 4*128
    float* sW1  = sIn  + 4 * TM;               // 4*128
    float* sB1  = sW1  + 4 * HID;              // 128
    float* sB2  = sB1  + HID;                  // 128
    float* sB3  = sB2  + HID;                  // 128
    float* sW4  = sB3  + HID;                  // 256
    float* sB4  = sW4  + 2 * HID;              // 4 (2 used)

    const int t    = threadIdx.x;
    const int mt   = (t & 7) | ((t >> 2) & 8);       // bits 0-2 + bit 5 -> 0..15
    const int jt   = ((t >> 3) & 3) | ((t >> 4) & 12); // bits 3-4 + bits 6-7 -> 0..15
    const int m0   = mt * 8;
    const int j0   = jt * 8;
    const int base = blockIdx.x * TM;

    // ---- stage inputs, W1/biases/W4, and W2 -> sW ----
    for (int i = t; i < TM; i += 256) {
        bool ok = (base + i < npts);
        sIn[0 * TM + i] = ok ? x [base + i] : 0.0f;
        sIn[1 * TM + i] = ok ? y [base + i] : 0.0f;
        sIn[2 * TM + i] = ok ? c1[base + i] : 0.0f;
        sIn[3 * TM + i] = ok ? c2[base + i] : 0.0f;
    }
    {
        const float4* src = (const float4*)W2;
        float4* dst = (float4*)sW;
#pragma unroll 4
        for (int i = t; i < HID * HID / 4; i += 256) dst[i] = src[i];
    }
    for (int i = t; i < 4 * HID; i += 256) sW1[i] = W1[i];
    if (t < HID) { sB1[t] = b1[t]; sB2[t] = b2[t]; sB3[t] = b3[t]; }
    if (t < 2 * HID) sW4[t] = W4[t];
    if (t < 2) sB4[t] = b4[t];
    __syncthreads();

    // ---- layer 1: [4] -> [128], write actA[k][m] ----
    {
        float im[4][8];
#pragma unroll
        for (int i = 0; i < 4; ++i) {
            float4 a = *(const float4*)(sIn + i * TM + m0);
            float4 b = *(const float4*)(sIn + i * TM + m0 + 4);
            im[i][0] = a.x; im[i][1] = a.y; im[i][2] = a.z; im[i][3] = a.w;
            im[i][4] = b.x; im[i][5] = b.y; im[i][6] = b.z; im[i][7] = b.w;
        }
#pragma unroll
        for (int jj = 0; jj < 8; ++jj) {
            int j = j0 + jj;
            float w0 = sW1[0 * HID + j], w1 = sW1[1 * HID + j];
            float w2 = sW1[2 * HID + j], w3 = sW1[3 * HID + j];
            float bb = sB1[j];
            float tt[8];
#pragma unroll
            for (int mi = 0; mi < 8; ++mi) {
                float v = bb;
                v = fmaf(im[0][mi], w0, v);
                v = fmaf(im[1][mi], w1, v);
                v = fmaf(im[2][mi], w2, v);
                v = fmaf(im[3][mi], w3, v);
                tt[mi] = my_tanh(v);
            }
            float* o = actA + j * P + m0;
            *(float4*)(o)     = make_float4(tt[0], tt[1], tt[2], tt[3]);
            *(float4*)(o + 4) = make_float4(tt[4], tt[5], tt[6], tt[7]);
        }
    }
    __syncthreads();

    // ---- layer 2: actA -> actB ([k][m]) using sW = W2 ----
    gemm_layer<false>(actA, actB, sW, sB2, m0, j0);
    __syncthreads();

    // ---- swap weights: W3 -> sW ----
    {
        const float4* src = (const float4*)W3;
        float4* dst = (float4*)sW;
#pragma unroll 4
        for (int i = t; i < HID * HID / 4; i += 256) dst[i] = src[i];
    }
    __syncthreads();

    // ---- layer 3: actB -> actA ([m][j]) using sW = W3 ----
    gemm_layer<true>(actB, actA, sW, sB3, m0, j0);
    __syncthreads();

    // ---- layer 4: out[m][0..1] from actA rows ----
    if (t < TM) {
        int m = t;
        float acc0 = sB4[0], acc1 = sB4[1];
        const float* hr = actA + m * P;
#pragma unroll 8
        for (int k = 0; k < HID; k += 4) {
            float4 h  = *(const float4*)(hr + k);
            float4 wa = *(const float4*)(sW4 + 2 * k);      // w4[k][0],w4[k][1],w4[k+1][0],w4[k+1][1]
            float4 wb = *(const float4*)(sW4 + 2 * k + 4);
            acc0 = fmaf(h.x, wa.x, acc0); acc1 = fmaf(h.x, wa.y, acc1);
            acc0 = fmaf(h.y, wa.z, acc0); acc1 = fmaf(h.y, wa.w, acc1);
            acc0 = fmaf(h.z, wb.x, acc0); acc1 = fmaf(h.z, wb.y, acc1);
            acc0 = fmaf(h.w, wb.z, acc0); acc1 = fmaf(h.w, wb.w, acc1);
        }
        if (base + m < npts) {
            float2 o; o.x = acc0; o.y = acc1;
            *(float2*)(out + (size_t)(base + m) * 2) = o;
        }
    }
}

extern "C" void kernel_launch(void* const* d_in, const int* in_sizes, int n_in,
                              void* d_out, int out_size) {
    const float* x  = (const float*)d_in[0];
    const float* y  = (const float*)d_in[1];
    const float* c1 = (const float*)d_in[2];
    const float* c2 = (const float*)d_in[3];
    const float* W1 = (const float*)d_in[4];
    const float* b1 = (const float*)d_in[5];
    const float* W2 = (const float*)d_in[6];
    const float* b2 = (const float*)d_in[7];
    const float* W3 = (const float*)d_in[8];
    const float* b3 = (const float*)d_in[9];
    const float* W4 = (const float*)d_in[10];
    const float* b4 = (const float*)d_in[11];
    float* out = (float*)d_out;

    const int npts = in_sizes[0];
    const int grid = (npts + TM - 1) / TM;
    const size_t smem = (size_t)(2 * HID * P + HID * HID + 4 * TM + 4 * HID
                                 + 3 * HID + 2 * HID + 4) * sizeof(float);

    cudaFuncSetAttribute(mlp_kernel, cudaFuncAttributeMaxDynamicSharedMemorySize, (int)smem);

    mlp_kernel<<<grid, 256, smem>>>(x, y, c1, c2, W1, b1, W2, b2, W3, b3, W4, b4,
                                    out, npts);
}

// round 6
// speedup vs baseline: 1.4965x; 1.0024x over previous
#include <cuda_runtime.h>
#include <math.h>

// MLP: [N,4] -> tanh(@W1[4,128]) -> tanh(@W2[128,128]) -> tanh(@W3[128,128]) -> @W4[128,2]
// N = 524288.  R4: 8x8 register tiling + packed fp32x2 FFMA (fma.rn.f32x2).
//
// CTA = 128 points x 128 neurons, 256 threads, thread tile = 8m x 8j.
// Activations ping-pong in smem as [row][col] pitch-132 buffers:
//   L1 out / L2 out : [k][m]   (k = neuron of producing layer)
//   L3 out          : [m][j]   (so layer-4 reads contiguous rows)
// Current layer weights (64KB) are staged into smem before each big layer.

#define TM   128
#define HID  128
#define P    132   // pitch in floats (16B-aligned rows)
typedef unsigned long long u64;

__device__ __forceinline__ u64 pack_dup(float x) {
    u64 r; asm("mov.b64 %0, {%1, %1};" : "=l"(r) : "f"(x)); return r;
}
__device__ __forceinline__ void unpack2(u64 v, float &lo, float &hi) {
    asm("mov.b64 {%0, %1}, %2;" : "=f"(lo), "=f"(hi) : "l"(v));
}
// d.lo += a.lo*b.lo ; d.hi += a.hi*b.hi   (packed fp32 FMA, sm_100+)
__device__ __forceinline__ void ffma2(u64 &d, u64 a, u64 b) {
    asm("fma.rn.f32x2 %0, %1, %2, %0;" : "+l"(d) : "l"(a), "l"(b));
}

__device__ __forceinline__ float my_tanh(float v) {
    float av = fminf(fabsf(v), 15.0f);
    float e  = __expf(2.0f * av);
    float r  = 1.0f - __fdividef(2.0f, e + 1.0f);
    return copysignf(r, v);
}

// One 128x128x128 layer: out = tanh(in^T W + b), thread tile 8m x 8j.
// acc pairs are over m (packed from u64 loads); weights are dup-packed.
template<bool ROW_IS_M>
__device__ __forceinline__ void gemm_layer(const float* __restrict__ aIn,
                                           float* __restrict__ aOut,
                                           const float* __restrict__ sWp,
                                           const float* __restrict__ bias,
                                           int m0, int j0) {
    u64 acc[8][4];
#pragma unroll
    for (int jj = 0; jj < 8; ++jj) {
        u64 bb = pack_dup(bias[j0 + jj]);
#pragma unroll
        for (int mp = 0; mp < 4; ++mp) acc[jj][mp] = bb;
    }

#pragma unroll 4
    for (int k = 0; k < HID; ++k) {
        const float* ar = aIn + k * P + m0;
        ulonglong2 aA = *(const ulonglong2*)(ar);       // pairs (m0,m0+1),(m0+2,m0+3)
        ulonglong2 aB = *(const ulonglong2*)(ar + 4);   // pairs (m0+4..7)
        const float* wr = sWp + (k << 7) + j0;
        float4 w0 = *(const float4*)(wr);
        float4 w1 = *(const float4*)(wr + 4);

        u64 av[4] = { aA.x, aA.y, aB.x, aB.y };
        u64 wd[8];
        wd[0] = pack_dup(w0.x); wd[1] = pack_dup(w0.y);
        wd[2] = pack_dup(w0.z); wd[3] = pack_dup(w0.w);
        wd[4] = pack_dup(w1.x); wd[5] = pack_dup(w1.y);
        wd[6] = pack_dup(w1.z); wd[7] = pack_dup(w1.w);

#pragma unroll
        for (int jj = 0; jj < 8; ++jj)
#pragma unroll
            for (int mp = 0; mp < 4; ++mp)
                ffma2(acc[jj][mp], av[mp], wd[jj]);
    }

    if (!ROW_IS_M) {
        // store as [j][m]
#pragma unroll
        for (int jj = 0; jj < 8; ++jj) {
            float t[8];
#pragma unroll
            for (int mp = 0; mp < 4; ++mp) {
                float lo, hi; unpack2(acc[jj][mp], lo, hi);
                t[2 * mp]     = my_tanh(lo);
                t[2 * mp + 1] = my_tanh(hi);
            }
            float* o = aOut + (j0 + jj) * P + m0;
            *(float4*)(o)     = make_float4(t[0], t[1], t[2], t[3]);
            *(float4*)(o + 4) = make_float4(t[4], t[5], t[6], t[7]);
        }
    } else {
        // store as [m][j]
#pragma unroll
        for (int mp = 0; mp < 4; ++mp) {
            float tl[8], th[8];
#pragma unroll
            for (int jj = 0; jj < 8; ++jj) {
                float lo, hi; unpack2(acc[jj][mp], lo, hi);
                tl[jj] = my_tanh(lo);
                th[jj] = my_tanh(hi);
            }
            float* o0 = aOut + (m0 + 2 * mp) * P + j0;
            *(float4*)(o0)     = make_float4(tl[0], tl[1], tl[2], tl[3]);
            *(float4*)(o0 + 4) = make_float4(tl[4], tl[5], tl[6], tl[7]);
            float* o1 = aOut + (m0 + 2 * mp + 1) * P + j0;
            *(float4*)(o1)     = make_float4(th[0], th[1], th[2], th[3]);
            *(float4*)(o1 + 4) = make_float4(th[4], th[5], th[6], th[7]);
        }
    }
}

__global__ __launch_bounds__(256)
void mlp_kernel(const float* __restrict__ x,  const float* __restrict__ y,
                const float* __restrict__ c1, const float* __restrict__ c2,
                const float* __restrict__ W1, const float* __restrict__ b1,
                const float* __restrict__ W2, const float* __restrict__ b2,
                const float* __restrict__ W3, const float* __restrict__ b3,
                const float* __restrict__ W4, const float* __restrict__ b4,
                float* __restrict__ out, int npts) {
    extern __shared__ float sm[];
    float* actA = sm;                          // 128*P
    float* actB = actA + HID * P;              // 128*P
    float* sW   = actB + HID * P;              // 128*128
    float* sIn  = sW   + HID * HID;            // 4*128
    float* sW1  = sIn  + 4 * TM;               // 4*128
    float* sB1  = sW1  + 4 * HID;              // 128
    float* sB2  = sB1  + HID;                  // 128
    float* sB3  = sB2  + HID;                  // 128
    float* sW4  = sB3  + HID;                  // 256
    float* sB4  = sW4  + 2 * HID;              // 4 (2 used)

    const int t    = threadIdx.x;
    const int mt   = (t & 7) | ((t >> 2) & 8);       // bits 0-2 + bit 5 -> 0..15
    const int jt   = ((t >> 3) & 3) | ((t >> 4) & 12); // bits 3-4 + bits 6-7 -> 0..15
    const int m0   = mt * 8;
    const int j0   = jt * 8;
    const int base = blockIdx.x * TM;

    // ---- stage inputs, W1/biases/W4, and W2 -> sW ----
    for (int i = t; i < TM; i += 256) {
        bool ok = (base + i < npts);
        sIn[0 * TM + i] = ok ? x [base + i] : 0.0f;
        sIn[1 * TM + i] = ok ? y [base + i] : 0.0f;
        sIn[2 * TM + i] = ok ? c1[base + i] : 0.0f;
        sIn[3 * TM + i] = ok ? c2[base + i] : 0.0f;
    }
    {
        const float4* src = (const float4*)W2;
        float4* dst = (float4*)sW;
#pragma unroll 4
        for (int i = t; i < HID * HID / 4; i += 256) dst[i] = src[i];
    }
    for (int i = t; i < 4 * HID; i += 256) sW1[i] = W1[i];
    if (t < HID) { sB1[t] = b1[t]; sB2[t] = b2[t]; sB3[t] = b3[t]; }
    if (t < 2 * HID) sW4[t] = W4[t];
    if (t < 2) sB4[t] = b4[t];
    __syncthreads();

    // ---- layer 1: [4] -> [128], write actA[k][m] ----
    {
        float im[4][8];
#pragma unroll
        for (int i = 0; i < 4; ++i) {
            float4 a = *(const float4*)(sIn + i * TM + m0);
            float4 b = *(const float4*)(sIn + i * TM + m0 + 4);
            im[i][0] = a.x; im[i][1] = a.y; im[i][2] = a.z; im[i][3] = a.w;
            im[i][4] = b.x; im[i][5] = b.y; im[i][6] = b.z; im[i][7] = b.w;
        }
#pragma unroll
        for (int jj = 0; jj < 8; ++jj) {
            int j = j0 + jj;
            float w0 = sW1[0 * HID + j], w1 = sW1[1 * HID + j];
            float w2 = sW1[2 * HID + j], w3 = sW1[3 * HID + j];
            float bb = sB1[j];
            float tt[8];
#pragma unroll
            for (int mi = 0; mi < 8; ++mi) {
                float v = bb;
                v = fmaf(im[0][mi], w0, v);
                v = fmaf(im[1][mi], w1, v);
                v = fmaf(im[2][mi], w2, v);
                v = fmaf(im[3][mi], w3, v);
                tt[mi] = my_tanh(v);
            }
            float* o = actA + j * P + m0;
            *(float4*)(o)     = make_float4(tt[0], tt[1], tt[2], tt[3]);
            *(float4*)(o + 4) = make_float4(tt[4], tt[5], tt[6], tt[7]);
        }
    }
    __syncthreads();

    // ---- layer 2: actA -> actB ([k][m]) using sW = W2 ----
    gemm_layer<false>(actA, actB, sW, sB2, m0, j0);
    __syncthreads();

    // ---- swap weights: W3 -> sW ----
    {
        const float4* src = (const float4*)W3;
        float4* dst = (float4*)sW;
#pragma unroll 4
        for (int i = t; i < HID * HID / 4; i += 256) dst[i] = src[i];
    }
    __syncthreads();

    // ---- layer 3: actB -> actA ([m][j]) using sW = W3 ----
    gemm_layer<true>(actB, actA, sW, sB3, m0, j0);
    __syncthreads();

    // ---- layer 4: out[m][0..1] from actA rows ----
    if (t < TM) {
        int m = t;
        float acc0 = sB4[0], acc1 = sB4[1];
        const float* hr = actA + m * P;
#pragma unroll 8
        for (int k = 0; k < HID; k += 4) {
            float4 h  = *(const float4*)(hr + k);
            float4 wa = *(const float4*)(sW4 + 2 * k);      // w4[k][0],w4[k][1],w4[k+1][0],w4[k+1][1]
            float4 wb = *(const float4*)(sW4 + 2 * k + 4);
            acc0 = fmaf(h.x, wa.x, acc0); acc1 = fmaf(h.x, wa.y, acc1);
            acc0 = fmaf(h.y, wa.z, acc0); acc1 = fmaf(h.y, wa.w, acc1);
            acc0 = fmaf(h.z, wb.x, acc0); acc1 = fmaf(h.z, wb.y, acc1);
            acc0 = fmaf(h.w, wb.z, acc0); acc1 = fmaf(h.w, wb.w, acc1);
        }
        if (base + m < npts) {
            float2 o; o.x = acc0; o.y = acc1;
            *(float2*)(out + (size_t)(base + m) * 2) = o;
        }
    }
}

extern "C" void kernel_launch(void* const* d_in, const int* in_sizes, int n_in,
                              void* d_out, int out_size) {
    const float* x  = (const float*)d_in[0];
    const float* y  = (const float*)d_in[1];
    const float* c1 = (const float*)d_in[2];
    const float* c2 = (const float*)d_in[3];
    const float* W1 = (const float*)d_in[4];
    const float* b1 = (const float*)d_in[5];
    const float* W2 = (const float*)d_in[6];
    const float* b2 = (const float*)d_in[7];
    const float* W3 = (const float*)d_in[8];
    const float* b3 = (const float*)d_in[9];
    const float* W4 = (const float*)d_in[10];
    const float* b4 = (const float*)d_in[11];
    float* out = (float*)d_out;

    const int npts = in_sizes[0];
    const int grid = (npts + TM - 1) / TM;
    const size_t smem = (size_t)(2 * HID * P + HID * HID + 4 * TM + 4 * HID
                                 + 3 * HID + 2 * HID + 4) * sizeof(float);

    cudaFuncSetAttribute(mlp_kernel, cudaFuncAttributeMaxDynamicSharedMemorySize, (int)smem);

    mlp_kernel<<<grid, 256, smem>>>(x, y, c1, c2, W1, b1, W2, b2, W3, b3, W4, b4,
                                    out, npts);
}

// round 8
// speedup vs baseline: 3.6363x; 2.4298x over previous
#include <cuda_runtime.h>
#include <cstdint>

// MLP [N,4]->128->128->128->2, tanh; N=524288.
// R7: warp-level bf16 HMMA (mma.sync m16n8k16) with 3-product hi/lo split.
// Persistent CTAs; weights resident in smem; warp-autonomous layers (no block syncs
// in the tile loop: warp w owns m-rows [16w,16w+16) end-to-end).

#define HID 128
#define TM  128
#define RPITCH 272u            // row pitch in bytes (136 bf16): 272 % 128 = 16 -> conflict-free ldmatrix

// smem byte offsets
#define A_HI   0u              // A tiles, 128 rows x 272B
#define A_LO   34816u
#define W2H    69632u          // W^T tiles [j][k] bf16, hi/lo
#define W2L    104448u
#define W3H    139264u
#define W3L    174080u
#define SW1_O  208896u         // 512 f
#define SB1_O  210944u         // 128 f
#define SB2_O  211456u
#define SB3_O  211968u
#define SW4_O  212480u         // 256 f
#define SMEM_BYTES 213504u

typedef uint32_t u32;

__device__ __forceinline__ u32 smem_u32(const void* p) {
    u32 a;
    asm("{ .reg .u64 t; cvta.to.shared.u64 t, %1; cvt.u32.u64 %0, t; }" : "=r"(a) : "l"(p));
    return a;
}

#define LDSM4(r0, r1, r2, r3, addr) \
    asm volatile("ldmatrix.sync.aligned.m8n8.x4.shared.b16 {%0,%1,%2,%3}, [%4];" \
                 : "=r"(r0), "=r"(r1), "=r"(r2), "=r"(r3) : "r"(addr))

#define MMA16816(d, a0, a1, a2, a3, b0, b1) \
    asm volatile("mma.sync.aligned.m16n8k16.row.col.f32.bf16.bf16.f32 " \
                 "{%0,%1,%2,%3}, {%4,%5,%6,%7}, {%8,%9}, {%0,%1,%2,%3};" \
                 : "+f"((d)[0]), "+f"((d)[1]), "+f"((d)[2]), "+f"((d)[3]) \
                 : "r"(a0), "r"(a1), "r"(a2), "r"(a3), "r"(b0), "r"(b1))

__device__ __forceinline__ float tanh_f(float v) {
    float vc = fminf(fmaxf(v, -15.0f), 15.0f);
    float e  = __expf(2.0f * vc);
    return 1.0f - __fdividef(2.0f, e + 1.0f);
}

// fp32 pair -> (hi = truncated bf16x2, lo = rn bf16x2 of residual); v0 -> low half
__device__ __forceinline__ void split_pair(float v0, float v1, u32& hp, u32& lp) {
    u32 u0 = __float_as_uint(v0), u1 = __float_as_uint(v1);
    hp = (u0 >> 16) | (u1 & 0xFFFF0000u);
    float l0 = v0 - __uint_as_float(u0 & 0xFFFF0000u);
    float l1 = v1 - __uint_as_float(u1 & 0xFFFF0000u);
    asm("cvt.rn.bf16x2.f32 %0, %1, %2;" : "=r"(lp) : "f"(l1), "f"(l0));
}

// stage W[k][j] (128x128 f32, j contiguous) -> transposed split bf16 tiles [j][k]
__device__ __forceinline__ void stage_weights(char* sm, u32 hiOff, u32 loOff,
                                              const float* __restrict__ Wg, int t) {
    for (int idx = t; idx < 64 * 128; idx += 256) {
        int j = idx & 127, k = (idx >> 7) << 1;
        float w0 = Wg[k * HID + j], w1 = Wg[(k + 1) * HID + j];
        u32 hp, lp;
        split_pair(w0, w1, hp, lp);
        u32 off = (u32)j * RPITCH + (u32)k * 2u;
        *(u32*)(sm + hiOff + off) = hp;
        *(u32*)(sm + loOff + off) = lp;
    }
}

// one 128x128x128 layer for this warp's 16-row stripe; acc[16][4] in registers
__device__ __forceinline__ void hmma_layer(u32 aHiB, u32 aLoB, u32 wHiB, u32 wLoB,
                                           u32 offA, u32 offB, float acc[16][4]) {
#pragma unroll
    for (int nt = 0; nt < 16; ++nt)
#pragma unroll
        for (int i = 0; i < 4; ++i) acc[nt][i] = 0.0f;

#pragma unroll 1
    for (int ks = 0; ks < 8; ++ks) {
        const u32 kb = (u32)ks * 32u;
        u32 bh[8][4], bl[8][4];
#pragma unroll
        for (int nt = 0; nt < 8; ++nt) {
            u32 ab = wHiB + (u32)nt * (16u * RPITCH) + kb + offB;
            LDSM4(bh[nt][0], bh[nt][1], bh[nt][2], bh[nt][3], ab);
            u32 lb = wLoB + (u32)nt * (16u * RPITCH) + kb + offB;
            LDSM4(bl[nt][0], bl[nt][1], bl[nt][2], bl[nt][3], lb);
        }
        u32 ah[4], al[4];
        LDSM4(ah[0], ah[1], ah[2], ah[3], aHiB + kb + offA);
        LDSM4(al[0], al[1], al[2], al[3], aLoB + kb + offA);

#pragma unroll
        for (int nt = 0; nt < 8; ++nt) {
            MMA16816(acc[2 * nt],     ah[0], ah[1], ah[2], ah[3], bh[nt][0], bh[nt][1]);
            MMA16816(acc[2 * nt],     al[0], al[1], al[2], al[3], bh[nt][0], bh[nt][1]);
            MMA16816(acc[2 * nt],     ah[0], ah[1], ah[2], ah[3], bl[nt][0], bl[nt][1]);
            MMA16816(acc[2 * nt + 1], ah[0], ah[1], ah[2], ah[3], bh[nt][2], bh[nt][3]);
            MMA16816(acc[2 * nt + 1], al[0], al[1], al[2], al[3], bh[nt][2], bh[nt][3]);
            MMA16816(acc[2 * nt + 1], ah[0], ah[1], ah[2], ah[3], bl[nt][2], bl[nt][3]);
        }
    }
}

__global__ __launch_bounds__(256, 1)
void mlp_hmma(const float* __restrict__ X,  const float* __restrict__ Y,
              const float* __restrict__ C1, const float* __restrict__ C2,
              const float* __restrict__ W1, const float* __restrict__ b1,
              const float* __restrict__ W2, const float* __restrict__ b2,
              const float* __restrict__ W3, const float* __restrict__ b3,
              const float* __restrict__ W4, const float* __restrict__ b4,
              float* __restrict__ out, int npts, int ntiles) {
    extern __shared__ __align__(128) char sm[];
    const u32 smB = smem_u32(sm);
    const int t = threadIdx.x, w = t >> 5, lane = t & 31;

    float* sW1f = (float*)(sm + SW1_O);
    float* sB1f = (float*)(sm + SB1_O);
    float* sB2f = (float*)(sm + SB2_O);
    float* sB3f = (float*)(sm + SB3_O);
    float* sW4f = (float*)(sm + SW4_O);

    // ---- one-time staging ----
    for (int i = t; i < 512; i += 256) sW1f[i] = W1[i];
    if (t < 128) { sB1f[t] = b1[t]; sB2f[t] = b2[t]; sB3f[t] = b3[t]; }
    if (t < 256) sW4f[t] = W4[t];
    stage_weights(sm, W2H, W2L, W2, t);
    stage_weights(sm, W3H, W3L, W3, t);
    const float b40 = b4[0], b41 = b4[1];
    __syncthreads();

    // per-lane ldmatrix address offsets (bytes)
    const u32 offA = (u32)(((lane & 7) + ((lane >> 3) & 1) * 8) * RPITCH
                           + ((lane >> 4) & 1) * 16);
    const u32 offB = (u32)(((lane & 7) + ((lane >> 4) & 1) * 8) * RPITCH
                           + ((lane >> 3) & 1) * 16);
    const int m0   = w * 16;                       // this warp's row stripe
    const u32 aHiB = smB + A_HI + (u32)m0 * RPITCH;
    const u32 aLoB = smB + A_LO + (u32)m0 * RPITCH;
    const int qr   = lane >> 2;                    // row within stripe (d-frag row)
    const int qc   = (lane & 3) * 2;               // col pair base

    for (int tile = blockIdx.x; tile < ntiles; tile += gridDim.x) {
        const int base = tile * TM;

        // ---- layer 1: inputs -> split A tiles (thread: row m=t>>1, half t&1) ----
        {
            const int m = t >> 1, half = t & 1, jb = half << 6;
            const bool ok = (base + m) < npts;
            const float xv = ok ? X[base + m] : 0.f, yv = ok ? Y[base + m] : 0.f;
            const float a1 = ok ? C1[base + m] : 0.f, a2 = ok ? C2[base + m] : 0.f;
            char* hiP = sm + A_HI + (u32)m * RPITCH + (u32)half * 128u;
            char* loP = sm + A_LO + (u32)m * RPITCH + (u32)half * 128u;
#pragma unroll
            for (int i = 0; i < 32; ++i) {
                int j0 = jb + 2 * i;
                float s0 = sB1f[j0];
                s0 = fmaf(xv, sW1f[j0], s0);
                s0 = fmaf(yv, sW1f[HID + j0], s0);
                s0 = fmaf(a1, sW1f[2 * HID + j0], s0);
                s0 = fmaf(a2, sW1f[3 * HID + j0], s0);
                float s1 = sB1f[j0 + 1];
                s1 = fmaf(xv, sW1f[j0 + 1], s1);
                s1 = fmaf(yv, sW1f[HID + j0 + 1], s1);
                s1 = fmaf(a1, sW1f[2 * HID + j0 + 1], s1);
                s1 = fmaf(a2, sW1f[3 * HID + j0 + 1], s1);
                u32 hp, lp;
                split_pair(tanh_f(s0), tanh_f(s1), hp, lp);
                *(u32*)(hiP + 4 * i) = hp;
                *(u32*)(loP + 4 * i) = lp;
            }
        }
        __syncwarp();

        // ---- layer 2: HMMA + tanh epilogue back into A tiles ----
        {
            float acc[16][4];
            hmma_layer(aHiB, aLoB, smB + W2H, smB + W2L, offA, offB, acc);
            __syncwarp();   // all lanes done reading A before overwrite
#pragma unroll
            for (int nt = 0; nt < 16; ++nt) {
                int j0 = nt * 8 + qc;
                float v0 = tanh_f(acc[nt][0] + sB2f[j0]);
                float v1 = tanh_f(acc[nt][1] + sB2f[j0 + 1]);
                float v2 = tanh_f(acc[nt][2] + sB2f[j0]);
                float v3 = tanh_f(acc[nt][3] + sB2f[j0 + 1]);
                u32 hp, lp;
                u32 o0 = (u32)(m0 + qr) * RPITCH + (u32)nt * 16u + (u32)(lane & 3) * 4u;
                split_pair(v0, v1, hp, lp);
                *(u32*)(sm + A_HI + o0) = hp;
                *(u32*)(sm + A_LO + o0) = lp;
                u32 o1 = o0 + 8u * RPITCH;
                split_pair(v2, v3, hp, lp);
                *(u32*)(sm + A_HI + o1) = hp;
                *(u32*)(sm + A_LO + o1) = lp;
            }
        }
        __syncwarp();

        // ---- layer 3 HMMA + fused tanh + layer-4 dot (all in registers) ----
        {
            float acc[16][4];
            hmma_layer(aHiB, aLoB, smB + W3H, smB + W3L, offA, offB, acc);
            float s00 = 0.f, s01 = 0.f, s10 = 0.f, s11 = 0.f;
#pragma unroll
            for (int nt = 0; nt < 16; ++nt) {
                int j0 = nt * 8 + qc;
                float h0 = tanh_f(acc[nt][0] + sB3f[j0]);
                float h1 = tanh_f(acc[nt][1] + sB3f[j0 + 1]);
                float h2 = tanh_f(acc[nt][2] + sB3f[j0]);
                float h3 = tanh_f(acc[nt][3] + sB3f[j0 + 1]);
                float2 w0 = *(const float2*)(sW4f + 2 * j0);
                float2 w1 = *(const float2*)(sW4f + 2 * j0 + 2);
                s00 = fmaf(h0, w0.x, s00); s01 = fmaf(h0, w0.y, s01);
                s00 = fmaf(h1, w1.x, s00); s01 = fmaf(h1, w1.y, s01);
                s10 = fmaf(h2, w0.x, s10); s11 = fmaf(h2, w0.y, s11);
                s10 = fmaf(h3, w1.x, s10); s11 = fmaf(h3, w1.y, s11);
            }
            // reduce across the 4 lanes of each row group
#pragma unroll
            for (int d = 1; d <= 2; d <<= 1) {
                s00 += __shfl_xor_sync(0xFFFFFFFFu, s00, d);
                s01 += __shfl_xor_sync(0xFFFFFFFFu, s01, d);
                s10 += __shfl_xor_sync(0xFFFFFFFFu, s10, d);
                s11 += __shfl_xor_sync(0xFFFFFFFFu, s11, d);
            }
            if ((lane & 3) == 0) {
                int mA = base + m0 + qr, mB = mA + 8;
                if (mA < npts)
                    *(float2*)(out + 2 * (size_t)mA) = make_float2(b40 + s00, b41 + s01);
                if (mB < npts)
                    *(float2*)(out + 2 * (size_t)mB) = make_float2(b40 + s10, b41 + s11);
            }
        }
        __syncwarp();   // A tiles fully consumed before next tile's layer 1
    }
}

extern "C" void kernel_launch(void* const* d_in, const int* in_sizes, int n_in,
                              void* d_out, int out_size) {
    const float* x  = (const float*)d_in[0];
    const float* y  = (const float*)d_in[1];
    const float* c1 = (const float*)d_in[2];
    const float* c2 = (const float*)d_in[3];
    const float* W1 = (const float*)d_in[4];
    const float* b1 = (const float*)d_in[5];
    const float* W2 = (const float*)d_in[6];
    const float* b2 = (const float*)d_in[7];
    const float* W3 = (const float*)d_in[8];
    const float* b3 = (const float*)d_in[9];
    const float* W4 = (const float*)d_in[10];
    const float* b4 = (const float*)d_in[11];
    float* out = (float*)d_out;

    const int npts   = in_sizes[0];
    const int ntiles = (npts + TM - 1) / TM;

    int dev = 0, sms = 148;
    cudaGetDevice(&dev);
    cudaDeviceGetAttribute(&sms, cudaDevAttrMultiProcessorCount, dev);
    int grid = sms < ntiles ? sms : ntiles;

    cudaFuncSetAttribute(mlp_hmma, cudaFuncAttributeMaxDynamicSharedMemorySize, SMEM_BYTES);
    mlp_hmma<<<grid, 256, SMEM_BYTES>>>(x, y, c1, c2, W1, b1, W2, b2, W3, b3, W4, b4,
                                        out, npts, ntiles);
}

// round 9
// speedup vs baseline: 3.6843x; 1.0132x over previous
#include <cuda_runtime.h>
#include <cstdint>

// MLP [N,4]->128->128->128->2, tanh; N=524288.
// R8: bf16 HMMA 3-product split with REGISTER-RESIDENT activation fragments.
// The D-fragment layout of layer L is exactly the A-fragment layout of layer L+1,
// so tanh + hi/lo split + repack happen in registers: no A smem at all.
// Warps fully independent (16-point micro-tiles), weights resident in smem.

#define HID 128
#define RPITCH 272u            // weight tile row pitch (bytes); 272 % 128 = 16 -> conflict-free ldmatrix

// smem byte offsets
#define W2H    0u              // W^T tiles [j][k] bf16 hi/lo, 128 rows x 272B
#define W2L    34816u
#define W3H    69632u
#define W3L    104448u
#define SW1_O  139264u         // 512 f
#define SB1_O  141312u         // 128 f
#define SB2_O  141824u
#define SB3_O  142336u
#define SW4_O  142848u         // 256 f
#define SMEM_BYTES 143872u

typedef uint32_t u32;

__device__ __forceinline__ u32 smem_u32(const void* p) {
    u32 a;
    asm("{ .reg .u64 t; cvta.to.shared.u64 t, %1; cvt.u32.u64 %0, t; }" : "=r"(a) : "l"(p));
    return a;
}

#define LDSM4(r0, r1, r2, r3, addr) \
    asm volatile("ldmatrix.sync.aligned.m8n8.x4.shared.b16 {%0,%1,%2,%3}, [%4];" \
                 : "=r"(r0), "=r"(r1), "=r"(r2), "=r"(r3) : "r"(addr))

#define MMA16816(d, a0, a1, a2, a3, b0, b1) \
    asm volatile("mma.sync.aligned.m16n8k16.row.col.f32.bf16.bf16.f32 " \
                 "{%0,%1,%2,%3}, {%4,%5,%6,%7}, {%8,%9}, {%0,%1,%2,%3};" \
                 : "+f"((d)[0]), "+f"((d)[1]), "+f"((d)[2]), "+f"((d)[3]) \
                 : "r"(a0), "r"(a1), "r"(a2), "r"(a3), "r"(b0), "r"(b1))

__device__ __forceinline__ float tanh_f(float v) {
    float vc = fminf(fmaxf(v, -15.0f), 15.0f);
    float e  = __expf(2.0f * vc);
    return 1.0f - __fdividef(2.0f, e + 1.0f);
}

// fp32 pair -> (hi = truncated bf16x2, lo = rn bf16x2 of residual); v0 -> low half
__device__ __forceinline__ void split_pair(float v0, float v1, u32& hp, u32& lp) {
    u32 u0 = __float_as_uint(v0), u1 = __float_as_uint(v1);
    hp = (u0 >> 16) | (u1 & 0xFFFF0000u);
    float l0 = v0 - __uint_as_float(u0 & 0xFFFF0000u);
    float l1 = v1 - __uint_as_float(u1 & 0xFFFF0000u);
    asm("cvt.rn.bf16x2.f32 %0, %1, %2;" : "=r"(lp) : "f"(l1), "f"(l0));
}

// stage W[k][j] (128x128 f32, j contiguous) -> transposed split bf16 tiles [j][k]
__device__ __forceinline__ void stage_weights(char* sm, u32 hiOff, u32 loOff,
                                              const float* __restrict__ Wg, int t) {
    for (int idx = t; idx < 64 * 128; idx += 256) {
        int j = idx & 127, k = (idx >> 7) << 1;
        float w0 = Wg[k * HID + j], w1 = Wg[(k + 1) * HID + j];
        u32 hp, lp;
        split_pair(w0, w1, hp, lp);
        u32 off = (u32)j * RPITCH + (u32)k * 2u;
        *(u32*)(sm + hiOff + off) = hp;
        *(u32*)(sm + loOff + off) = lp;
    }
}

// One 128x128x128 layer for this warp's 16-row stripe.
// A fragments (hi/lo) come from registers; B (weights) streamed via ldmatrix.
__device__ __forceinline__ void hmma_layer(const u32 ah[8][4], const u32 al[8][4],
                                           u32 wHb, u32 wLb, float acc[16][4]) {
#pragma unroll
    for (int nt = 0; nt < 16; ++nt)
#pragma unroll
        for (int i = 0; i < 4; ++i) acc[nt][i] = 0.0f;

#pragma unroll 1
    for (int ks = 0; ks < 8; ++ks) {
        const u32 kb = (u32)ks * 32u;
#pragma unroll
        for (int nt = 0; nt < 8; ++nt) {
            u32 bh0, bh1, bh2, bh3, bl0, bl1, bl2, bl3;
            LDSM4(bh0, bh1, bh2, bh3, wHb + (u32)nt * 4352u + kb);
            LDSM4(bl0, bl1, bl2, bl3, wLb + (u32)nt * 4352u + kb);
            // interleave the two accumulators to shorten dependency chains
            MMA16816(acc[2 * nt],     ah[ks][0], ah[ks][1], ah[ks][2], ah[ks][3], bh0, bh1);
            MMA16816(acc[2 * nt + 1], ah[ks][0], ah[ks][1], ah[ks][2], ah[ks][3], bh2, bh3);
            MMA16816(acc[2 * nt],     al[ks][0], al[ks][1], al[ks][2], al[ks][3], bh0, bh1);
            MMA16816(acc[2 * nt + 1], al[ks][0], al[ks][1], al[ks][2], al[ks][3], bh2, bh3);
            MMA16816(acc[2 * nt],     ah[ks][0], ah[ks][1], ah[ks][2], ah[ks][3], bl0, bl1);
            MMA16816(acc[2 * nt + 1], ah[ks][0], ah[ks][1], ah[ks][2], ah[ks][3], bl2, bl3);
        }
    }
}

__global__ __launch_bounds__(256, 1)
void mlp_hmma2(const float* __restrict__ X,  const float* __restrict__ Y,
               const float* __restrict__ C1, const float* __restrict__ C2,
               const float* __restrict__ W1, const float* __restrict__ b1,
               const float* __restrict__ W2, const float* __restrict__ b2,
               const float* __restrict__ W3, const float* __restrict__ b3,
               const float* __restrict__ W4, const float* __restrict__ b4,
               float* __restrict__ out, int npts) {
    extern __shared__ __align__(128) char sm[];
    const u32 smB = smem_u32(sm);
    const int t = threadIdx.x, w = t >> 5, lane = t & 31;

    float* sW1f = (float*)(sm + SW1_O);
    float* sB1f = (float*)(sm + SB1_O);
    float* sB2f = (float*)(sm + SB2_O);
    float* sB3f = (float*)(sm + SB3_O);
    float* sW4f = (float*)(sm + SW4_O);

    // ---- one-time staging ----
    for (int i = t; i < 512; i += 256) sW1f[i] = W1[i];
    if (t < 128) { sB1f[t] = b1[t]; sB2f[t] = b2[t]; sB3f[t] = b3[t]; }
    if (t < 256) sW4f[t] = W4[t];
    stage_weights(sm, W2H, W2L, W2, t);
    stage_weights(sm, W3H, W3L, W3, t);
    const float b40 = b4[0], b41 = b4[1];
    __syncthreads();

    const int qr = lane >> 2;           // fragment row within stripe
    const int qc = (lane & 3) * 2;      // fragment col pair base
    // per-lane ldmatrix offset for weight (B) tiles
    const u32 offB = (u32)(((lane & 7) + ((lane >> 4) & 1) * 8) * RPITCH
                           + ((lane >> 3) & 1) * 16);
    const u32 w2h = smB + W2H + offB, w2l = smB + W2L + offB;
    const u32 w3h = smB + W3H + offB, w3l = smB + W3L + offB;

    const int n16 = (npts + 15) >> 4;                 // 16-point micro-tiles
    const int gw  = blockIdx.x * 8 + w;               // global warp id
    const int nw  = gridDim.x * 8;

    for (int wt = gw; wt < n16; wt += nw) {
        const int r0 = wt * 16 + qr, r1 = r0 + 8;     // this lane's two rows
        const bool ok0 = r0 < npts, ok1 = r1 < npts;
        const float x0 = ok0 ? X[r0] : 0.f, y0 = ok0 ? Y[r0] : 0.f;
        const float p0 = ok0 ? C1[r0] : 0.f, q0 = ok0 ? C2[r0] : 0.f;
        const float x1 = ok1 ? X[r1] : 0.f, y1 = ok1 ? Y[r1] : 0.f;
        const float p1 = ok1 ? C1[r1] : 0.f, q1 = ok1 ? C2[r1] : 0.f;

        u32 ah[8][4], al[8][4];

        // ---- layer 1: compute directly in A-fragment pattern ----
#pragma unroll
        for (int nt = 0; nt < 16; ++nt) {
            const int j0 = nt * 8 + qc;
            const float wa0 = sW1f[j0],           wb0 = sW1f[HID + j0];
            const float wc0 = sW1f[2 * HID + j0], wd0 = sW1f[3 * HID + j0];
            const float wa1 = sW1f[j0 + 1],           wb1 = sW1f[HID + j0 + 1];
            const float wc1 = sW1f[2 * HID + j0 + 1], wd1 = sW1f[3 * HID + j0 + 1];
            const float bb0 = sB1f[j0], bb1 = sB1f[j0 + 1];

            float v0 = fmaf(q0, wd0, fmaf(p0, wc0, fmaf(y0, wb0, fmaf(x0, wa0, bb0))));
            float v1 = fmaf(q0, wd1, fmaf(p0, wc1, fmaf(y0, wb1, fmaf(x0, wa1, bb1))));
            float v2 = fmaf(q1, wd0, fmaf(p1, wc0, fmaf(y1, wb0, fmaf(x1, wa0, bb0))));
            float v3 = fmaf(q1, wd1, fmaf(p1, wc1, fmaf(y1, wb1, fmaf(x1, wa1, bb1))));
            v0 = tanh_f(v0); v1 = tanh_f(v1); v2 = tanh_f(v2); v3 = tanh_f(v3);

            const int ks = nt >> 1, o = (nt & 1) * 2;
            split_pair(v0, v1, ah[ks][o],     al[ks][o]);
            split_pair(v2, v3, ah[ks][o + 1], al[ks][o + 1]);
        }

        float acc[16][4];

        // ---- layer 2: HMMA + in-register tanh/split repack ----
        hmma_layer(ah, al, w2h, w2l, acc);
#pragma unroll
        for (int nt = 0; nt < 16; ++nt) {
            const int j0 = nt * 8 + qc;
            float v0 = tanh_f(acc[nt][0] + sB2f[j0]);
            float v1 = tanh_f(acc[nt][1] + sB2f[j0 + 1]);
            float v2 = tanh_f(acc[nt][2] + sB2f[j0]);
            float v3 = tanh_f(acc[nt][3] + sB2f[j0 + 1]);
            const int ks = nt >> 1, o = (nt & 1) * 2;
            split_pair(v0, v1, ah[ks][o],     al[ks][o]);
            split_pair(v2, v3, ah[ks][o + 1], al[ks][o + 1]);
        }

        // ---- layer 3 HMMA + fused tanh + layer-4 dot (all in registers) ----
        hmma_layer(ah, al, w3h, w3l, acc);
        {
            float s00 = 0.f, s01 = 0.f, s10 = 0.f, s11 = 0.f;
#pragma unroll
            for (int nt = 0; nt < 16; ++nt) {
                const int j0 = nt * 8 + qc;
                float h0 = tanh_f(acc[nt][0] + sB3f[j0]);
                float h1 = tanh_f(acc[nt][1] + sB3f[j0 + 1]);
                float h2 = tanh_f(acc[nt][2] + sB3f[j0]);
                float h3 = tanh_f(acc[nt][3] + sB3f[j0 + 1]);
                float2 w0 = *(const float2*)(sW4f + 2 * j0);
                float2 w1 = *(const float2*)(sW4f + 2 * j0 + 2);
                s00 = fmaf(h0, w0.x, s00); s01 = fmaf(h0, w0.y, s01);
                s00 = fmaf(h1, w1.x, s00); s01 = fmaf(h1, w1.y, s01);
                s10 = fmaf(h2, w0.x, s10); s11 = fmaf(h2, w0.y, s11);
                s10 = fmaf(h3, w1.x, s10); s11 = fmaf(h3, w1.y, s11);
            }
#pragma unroll
            for (int d = 1; d <= 2; d <<= 1) {
                s00 += __shfl_xor_sync(0xFFFFFFFFu, s00, d);
                s01 += __shfl_xor_sync(0xFFFFFFFFu, s01, d);
                s10 += __shfl_xor_sync(0xFFFFFFFFu, s10, d);
                s11 += __shfl_xor_sync(0xFFFFFFFFu, s11, d);
            }
            if ((lane & 3) == 0) {
                if (ok0) *(float2*)(out + 2 * (size_t)r0) = make_float2(b40 + s00, b41 + s01);
                if (ok1) *(float2*)(out + 2 * (size_t)r1) = make_float2(b40 + s10, b41 + s11);
            }
        }
    }
}

extern "C" void kernel_launch(void* const* d_in, const int* in_sizes, int n_in,
                              void* d_out, int out_size) {
    const float* x  = (const float*)d_in[0];
    const float* y  = (const float*)d_in[1];
    const float* c1 = (const float*)d_in[2];
    const float* c2 = (const float*)d_in[3];
    const float* W1 = (const float*)d_in[4];
    const float* b1 = (const float*)d_in[5];
    const float* W2 = (const float*)d_in[6];
    const float* b2 = (const float*)d_in[7];
    const float* W3 = (const float*)d_in[8];
    const float* b3 = (const float*)d_in[9];
    const float* W4 = (const float*)d_in[10];
    const float* b4 = (const float*)d_in[11];
    float* out = (float*)d_out;

    const int npts = in_sizes[0];

    int dev = 0, sms = 148;
    cudaGetDevice(&dev);
    cudaDeviceGetAttribute(&sms, cudaDevAttrMultiProcessorCount, dev);
    int n16 = (npts + 15) / 16;
    int maxCtas = (n16 + 7) / 8;
    int grid = sms < maxCtas ? sms : maxCtas;

    cudaFuncSetAttribute(mlp_hmma2, cudaFuncAttributeMaxDynamicSharedMemorySize, SMEM_BYTES);
    mlp_hmma2<<<grid, 256, SMEM_BYTES>>>(x, y, c1, c2, W1, b1, W2, b2, W3, b3, W4, b4,
                                         out, npts);
}

// round 10
// speedup vs baseline: 3.7663x; 1.0223x over previous
#include <cuda_runtime.h>
#include <cstdint>

// MLP [N,4]->128->128->128->2, tanh; N=524288.
// R9: R8 algorithm (bf16 HMMA 3-product split, register-resident A fragments,
// warp-autonomous 16-point micro-tiles) with 384 threads/CTA (12 warps,
// 3 warps/SMSP) so MMA phases of one warp overlap MUFU/FMA epilogue phases
// of the others. Weights resident in smem (staged once per CTA).

#define HID 128
#define NTHREADS 384
#define NWARPS 12
#define RPITCH 272u            // weight tile row pitch (bytes); 272 % 128 = 16 -> conflict-free ldmatrix

// smem byte offsets
#define W2H    0u              // W^T tiles [j][k] bf16 hi/lo, 128 rows x 272B
#define W2L    34816u
#define W3H    69632u
#define W3L    104448u
#define SW1_O  139264u         // 512 f
#define SB1_O  141312u         // 128 f
#define SB2_O  141824u
#define SB3_O  142336u
#define SW4_O  142848u         // 256 f
#define SMEM_BYTES 143872u

typedef uint32_t u32;

__device__ __forceinline__ u32 smem_u32(const void* p) {
    u32 a;
    asm("{ .reg .u64 t; cvta.to.shared.u64 t, %1; cvt.u32.u64 %0, t; }" : "=r"(a) : "l"(p));
    return a;
}

#define LDSM4(r0, r1, r2, r3, addr) \
    asm volatile("ldmatrix.sync.aligned.m8n8.x4.shared.b16 {%0,%1,%2,%3}, [%4];" \
                 : "=r"(r0), "=r"(r1), "=r"(r2), "=r"(r3) : "r"(addr))

#define MMA16816(d, a0, a1, a2, a3, b0, b1) \
    asm volatile("mma.sync.aligned.m16n8k16.row.col.f32.bf16.bf16.f32 " \
                 "{%0,%1,%2,%3}, {%4,%5,%6,%7}, {%8,%9}, {%0,%1,%2,%3};" \
                 : "+f"((d)[0]), "+f"((d)[1]), "+f"((d)[2]), "+f"((d)[3]) \
                 : "r"(a0), "r"(a1), "r"(a2), "r"(a3), "r"(b0), "r"(b1))

__device__ __forceinline__ float tanh_f(float v) {
    float vc = fminf(fmaxf(v, -15.0f), 15.0f);
    float e  = __expf(2.0f * vc);
    return 1.0f - __fdividef(2.0f, e + 1.0f);
}

// fp32 pair -> (hi = truncated bf16x2, lo = rn bf16x2 of residual); v0 -> low half
__device__ __forceinline__ void split_pair(float v0, float v1, u32& hp, u32& lp) {
    u32 u0 = __float_as_uint(v0), u1 = __float_as_uint(v1);
    hp = (u0 >> 16) | (u1 & 0xFFFF0000u);
    float l0 = v0 - __uint_as_float(u0 & 0xFFFF0000u);
    float l1 = v1 - __uint_as_float(u1 & 0xFFFF0000u);
    asm("cvt.rn.bf16x2.f32 %0, %1, %2;" : "=r"(lp) : "f"(l1), "f"(l0));
}

// stage W[k][j] (128x128 f32, j contiguous) -> transposed split bf16 tiles [j][k]
__device__ __forceinline__ void stage_weights(char* sm, u32 hiOff, u32 loOff,
                                              const float* __restrict__ Wg, int t) {
    for (int idx = t; idx < 64 * 128; idx += NTHREADS) {
        int j = idx & 127, k = (idx >> 7) << 1;
        float w0 = Wg[k * HID + j], w1 = Wg[(k + 1) * HID + j];
        u32 hp, lp;
        split_pair(w0, w1, hp, lp);
        u32 off = (u32)j * RPITCH + (u32)k * 2u;
        *(u32*)(sm + hiOff + off) = hp;
        *(u32*)(sm + loOff + off) = lp;
    }
}

// One 128x128x128 layer for this warp's 16-row stripe.
// A fragments (hi/lo) in registers; B (weights) streamed via ldmatrix.
__device__ __forceinline__ void hmma_layer(const u32 ah[8][4], const u32 al[8][4],
                                           u32 wHb, u32 wLb, float acc[16][4]) {
#pragma unroll
    for (int nt = 0; nt < 16; ++nt)
#pragma unroll
        for (int i = 0; i < 4; ++i) acc[nt][i] = 0.0f;

#pragma unroll 1
    for (int ks = 0; ks < 8; ++ks) {
        const u32 kb = (u32)ks * 32u;
#pragma unroll
        for (int nt = 0; nt < 8; ++nt) {
            u32 bh0, bh1, bh2, bh3, bl0, bl1, bl2, bl3;
            LDSM4(bh0, bh1, bh2, bh3, wHb + (u32)nt * 4352u + kb);
            LDSM4(bl0, bl1, bl2, bl3, wLb + (u32)nt * 4352u + kb);
            // interleave the two accumulators to shorten dependency chains
            MMA16816(acc[2 * nt],     ah[ks][0], ah[ks][1], ah[ks][2], ah[ks][3], bh0, bh1);
            MMA16816(acc[2 * nt + 1], ah[ks][0], ah[ks][1], ah[ks][2], ah[ks][3], bh2, bh3);
            MMA16816(acc[2 * nt],     al[ks][0], al[ks][1], al[ks][2], al[ks][3], bh0, bh1);
            MMA16816(acc[2 * nt + 1], al[ks][0], al[ks][1], al[ks][2], al[ks][3], bh2, bh3);
            MMA16816(acc[2 * nt],     ah[ks][0], ah[ks][1], ah[ks][2], ah[ks][3], bl0, bl1);
            MMA16816(acc[2 * nt + 1], ah[ks][0], ah[ks][1], ah[ks][2], ah[ks][3], bl2, bl3);
        }
    }
}

__global__ __launch_bounds__(NTHREADS, 1)
void mlp_hmma3(const float* __restrict__ X,  const float* __restrict__ Y,
               const float* __restrict__ C1, const float* __restrict__ C2,
               const float* __restrict__ W1, const float* __restrict__ b1,
               const float* __restrict__ W2, const float* __restrict__ b2,
               const float* __restrict__ W3, const float* __restrict__ b3,
               const float* __restrict__ W4, const float* __restrict__ b4,
               float* __restrict__ out, int npts) {
    extern __shared__ __align__(128) char sm[];
    const u32 smB = smem_u32(sm);
    const int t = threadIdx.x, w = t >> 5, lane = t & 31;

    float* sW1f = (float*)(sm + SW1_O);
    float* sB1f = (float*)(sm + SB1_O);
    float* sB2f = (float*)(sm + SB2_O);
    float* sB3f = (float*)(sm + SB3_O);
    float* sW4f = (float*)(sm + SW4_O);

    // ---- one-time staging ----
    for (int i = t; i < 512; i += NTHREADS) sW1f[i] = W1[i];
    if (t < 128) { sB1f[t] = b1[t]; sB2f[t] = b2[t]; sB3f[t] = b3[t]; }
    if (t < 256) sW4f[t] = W4[t];
    stage_weights(sm, W2H, W2L, W2, t);
    stage_weights(sm, W3H, W3L, W3, t);
    const float b40 = b4[0], b41 = b4[1];
    __syncthreads();

    const int qr = lane >> 2;           // fragment row within stripe
    const int qc = (lane & 3) * 2;      // fragment col pair base
    // per-lane ldmatrix offset for weight (B) tiles
    const u32 offB = (u32)(((lane & 7) + ((lane >> 4) & 1) * 8) * RPITCH
                           + ((lane >> 3) & 1) * 16);
    const u32 w2h = smB + W2H + offB, w2l = smB + W2L + offB;
    const u32 w3h = smB + W3H + offB, w3l = smB + W3L + offB;

    const int n16 = (npts + 15) >> 4;                 // 16-point micro-tiles
    const int gw  = blockIdx.x * NWARPS + w;          // global warp id
    const int nw  = gridDim.x * NWARPS;

    for (int wt = gw; wt < n16; wt += nw) {
        const int r0 = wt * 16 + qr, r1 = r0 + 8;     // this lane's two rows
        const bool ok0 = r0 < npts, ok1 = r1 < npts;
        const float x0 = ok0 ? X[r0] : 0.f, y0 = ok0 ? Y[r0] : 0.f;
        const float p0 = ok0 ? C1[r0] : 0.f, q0 = ok0 ? C2[r0] : 0.f;
        const float x1 = ok1 ? X[r1] : 0.f, y1 = ok1 ? Y[r1] : 0.f;
        const float p1 = ok1 ? C1[r1] : 0.f, q1 = ok1 ? C2[r1] : 0.f;

        u32 ah[8][4], al[8][4];

        // ---- layer 1: compute directly in A-fragment pattern ----
#pragma unroll
        for (int nt = 0; nt < 16; ++nt) {
            const int j0 = nt * 8 + qc;
            const float wa0 = sW1f[j0],           wb0 = sW1f[HID + j0];
            const float wc0 = sW1f[2 * HID + j0], wd0 = sW1f[3 * HID + j0];
            const float wa1 = sW1f[j0 + 1],           wb1 = sW1f[HID + j0 + 1];
            const float wc1 = sW1f[2 * HID + j0 + 1], wd1 = sW1f[3 * HID + j0 + 1];
            const float bb0 = sB1f[j0], bb1 = sB1f[j0 + 1];

            float v0 = fmaf(q0, wd0, fmaf(p0, wc0, fmaf(y0, wb0, fmaf(x0, wa0, bb0))));
            float v1 = fmaf(q0, wd1, fmaf(p0, wc1, fmaf(y0, wb1, fmaf(x0, wa1, bb1))));
            float v2 = fmaf(q1, wd0, fmaf(p1, wc0, fmaf(y1, wb0, fmaf(x1, wa0, bb0))));
            float v3 = fmaf(q1, wd1, fmaf(p1, wc1, fmaf(y1, wb1, fmaf(x1, wa1, bb1))));
            v0 = tanh_f(v0); v1 = tanh_f(v1); v2 = tanh_f(v2); v3 = tanh_f(v3);

            const int ks = nt >> 1, o = (nt & 1) * 2;
            split_pair(v0, v1, ah[ks][o],     al[ks][o]);
            split_pair(v2, v3, ah[ks][o + 1], al[ks][o + 1]);
        }

        float acc[16][4];

        // ---- layer 2: HMMA + in-register tanh/split repack ----
        hmma_layer(ah, al, w2h, w2l, acc);
#pragma unroll
        for (int nt = 0; nt < 16; ++nt) {
            const int j0 = nt * 8 + qc;
            float v0 = tanh_f(acc[nt][0] + sB2f[j0]);
            float v1 = tanh_f(acc[nt][1] + sB2f[j0 + 1]);
            float v2 = tanh_f(acc[nt][2] + sB2f[j0]);
            float v3 = tanh_f(acc[nt][3] + sB2f[j0 + 1]);
            const int ks = nt >> 1, o = (nt & 1) * 2;
            split_pair(v0, v1, ah[ks][o],     al[ks][o]);
            split_pair(v2, v3, ah[ks][o + 1], al[ks][o + 1]);
        }

        // ---- layer 3 HMMA + fused tanh + layer-4 dot (all in registers) ----
        hmma_layer(ah, al, w3h, w3l, acc);
        {
            float s00 = 0.f, s01 = 0.f, s10 = 0.f, s11 = 0.f;
#pragma unroll
            for (int nt = 0; nt < 16; ++nt) {
                const int j0 = nt * 8 + qc;
                float h0 = tanh_f(acc[nt][0] + sB3f[j0]);
                float h1 = tanh_f(acc[nt][1] + sB3f[j0 + 1]);
                float h2 = tanh_f(acc[nt][2] + sB3f[j0]);
                float h3 = tanh_f(acc[nt][3] + sB3f[j0 + 1]);
                float2 w0 = *(const float2*)(sW4f + 2 * j0);
                float2 w1 = *(const float2*)(sW4f + 2 * j0 + 2);
                s00 = fmaf(h0, w0.x, s00); s01 = fmaf(h0, w0.y, s01);
                s00 = fmaf(h1, w1.x, s00); s01 = fmaf(h1, w1.y, s01);
                s10 = fmaf(h2, w0.x, s10); s11 = fmaf(h2, w0.y, s11);
                s10 = fmaf(h3, w1.x, s10); s11 = fmaf(h3, w1.y, s11);
            }
#pragma unroll
            for (int d = 1; d <= 2; d <<= 1) {
                s00 += __shfl_xor_sync(0xFFFFFFFFu, s00, d);
                s01 += __shfl_xor_sync(0xFFFFFFFFu, s01, d);
                s10 += __shfl_xor_sync(0xFFFFFFFFu, s10, d);
                s11 += __shfl_xor_sync(0xFFFFFFFFu, s11, d);
            }
            if ((lane & 3) == 0) {
                if (ok0) *(float2*)(out + 2 * (size_t)r0) = make_float2(b40 + s00, b41 + s01);
                if (ok1) *(float2*)(out + 2 * (size_t)r1) = make_float2(b40 + s10, b41 + s11);
            }
        }
    }
}

extern "C" void kernel_launch(void* const* d_in, const int* in_sizes, int n_in,
                              void* d_out, int out_size) {
    const float* x  = (const float*)d_in[0];
    const float* y  = (const float*)d_in[1];
    const float* c1 = (const float*)d_in[2];
    const float* c2 = (const float*)d_in[3];
    const float* W1 = (const float*)d_in[4];
    const float* b1 = (const float*)d_in[5];
    const float* W2 = (const float*)d_in[6];
    const float* b2 = (const float*)d_in[7];
    const float* W3 = (const float*)d_in[8];
    const float* b3 = (const float*)d_in[9];
    const float* W4 = (const float*)d_in[10];
    const float* b4 = (const float*)d_in[11];
    float* out = (float*)d_out;

    const int npts = in_sizes[0];

    int dev = 0, sms = 148;
    cudaGetDevice(&dev);
    cudaDeviceGetAttribute(&sms, cudaDevAttrMultiProcessorCount, dev);
    int n16 = (npts + 15) / 16;
    int maxCtas = (n16 + NWARPS - 1) / NWARPS;
    int grid = sms < maxCtas ? sms : maxCtas;

    cudaFuncSetAttribute(mlp_hmma3, cudaFuncAttributeMaxDynamicSharedMemorySize, SMEM_BYTES);
    mlp_hmma3<<<grid, NTHREADS, SMEM_BYTES>>>(x, y, c1, c2, W1, b1, W2, b2, W3, b3, W4, b4,
                                              out, npts);
}

// round 11
// speedup vs baseline: 4.3869x; 1.1648x over previous
#include <cuda_runtime.h>
#include <cstdint>

// MLP [N,4]->128->128->128->2, tanh; N=524288.
// R10: bf16 HMMA 3-product split, register-resident A fragments, and
// GROUP-INTERLEAVED epilogue: each 128-col layer is 4 n32 groups; group g's
// tanh/split overlaps group g+1's MMAs, so the tensor pipe never drains on
// a whole-layer epilogue. Bias folded into accumulator init; clamp-free tanh.

#define HID 128
#define NTHREADS 384
#define NWARPS 12
#define RPITCH 272u            // weight tile row pitch (bytes); conflict-free ldmatrix

// smem byte offsets
#define W2H    0u              // W^T tiles [j][k] bf16 hi/lo, 128 rows x 272B
#define W2L    34816u
#define W3H    69632u
#define W3L    104448u
#define SW1_O  139264u         // 512 f
#define SB1_O  141312u         // 128 f
#define SB2_O  141824u
#define SB3_O  142336u
#define SW4_O  142848u         // 256 f
#define SMEM_BYTES 143872u

typedef uint32_t u32;

__device__ __forceinline__ u32 smem_u32(const void* p) {
    u32 a;
    asm("{ .reg .u64 t; cvta.to.shared.u64 t, %1; cvt.u32.u64 %0, t; }" : "=r"(a) : "l"(p));
    return a;
}

#define LDSM4(r0, r1, r2, r3, addr) \
    asm volatile("ldmatrix.sync.aligned.m8n8.x4.shared.b16 {%0,%1,%2,%3}, [%4];" \
                 : "=r"(r0), "=r"(r1), "=r"(r2), "=r"(r3) : "r"(addr))

#define MMA16816(d, a0, a1, a2, a3, b0, b1) \
    asm volatile("mma.sync.aligned.m16n8k16.row.col.f32.bf16.bf16.f32 " \
                 "{%0,%1,%2,%3}, {%4,%5,%6,%7}, {%8,%9}, {%0,%1,%2,%3};" \
                 : "+f"((d)[0]), "+f"((d)[1]), "+f"((d)[2]), "+f"((d)[3]) \
                 : "r"(a0), "r"(a1), "r"(a2), "r"(a3), "r"(b0), "r"(b1))

// clamp-free: 1 - 2/(e^{2v}+1); e=inf -> 1, e=0 -> -1, both exact.
__device__ __forceinline__ float tanh_nc(float v) {
    float e = __expf(2.0f * v);
    return 1.0f - __fdividef(2.0f, e + 1.0f);
}

// fp32 pair -> (hi = truncated bf16x2, lo = rn bf16x2 of residual); v0 -> low half
__device__ __forceinline__ void split_pair(float v0, float v1, u32& hp, u32& lp) {
    u32 u0 = __float_as_uint(v0), u1 = __float_as_uint(v1);
    hp = (u0 >> 16) | (u1 & 0xFFFF0000u);
    float l0 = v0 - __uint_as_float(u0 & 0xFFFF0000u);
    float l1 = v1 - __uint_as_float(u1 & 0xFFFF0000u);
    asm("cvt.rn.bf16x2.f32 %0, %1, %2;" : "=r"(lp) : "f"(l1), "f"(l0));
}

// stage W[k][j] (128x128 f32, j contiguous) -> transposed split bf16 tiles [j][k]
__device__ __forceinline__ void stage_weights(char* sm, u32 hiOff, u32 loOff,
                                              const float* __restrict__ Wg, int t) {
    for (int idx = t; idx < 64 * 128; idx += NTHREADS) {
        int j = idx & 127, k = (idx >> 7) << 1;
        float w0 = Wg[k * HID + j], w1 = Wg[(k + 1) * HID + j];
        u32 hp, lp;
        split_pair(w0, w1, hp, lp);
        u32 off = (u32)j * RPITCH + (u32)k * 2u;
        *(u32*)(sm + hiOff + off) = hp;
        *(u32*)(sm + loOff + off) = lp;
    }
}

// 192 MMAs for one n32 group (n16 blocks 2g, 2g+1) of one layer.
// 4 accumulator quads, round-robin MMA order (dep distance 4 slots).
__device__ __forceinline__ void group_mma(const u32 ah[8][4], const u32 al[8][4],
                                          u32 wh, u32 wl, int g, float acc[4][4]) {
#pragma unroll
    for (int ks = 0; ks < 8; ++ks) {
        const u32 o0 = (u32)(2 * g)     * 4352u + (u32)ks * 32u;
        const u32 o1 = (u32)(2 * g + 1) * 4352u + (u32)ks * 32u;
        u32 h00, h01, h02, h03, h10, h11, h12, h13;
        u32 l00, l01, l02, l03, l10, l11, l12, l13;
        LDSM4(h00, h01, h02, h03, wh + o0);
        LDSM4(h10, h11, h12, h13, wh + o1);
        LDSM4(l00, l01, l02, l03, wl + o0);
        LDSM4(l10, l11, l12, l13, wl + o1);
        MMA16816(acc[0], ah[ks][0], ah[ks][1], ah[ks][2], ah[ks][3], h00, h01);
        MMA16816(acc[1], ah[ks][0], ah[ks][1], ah[ks][2], ah[ks][3], h02, h03);
        MMA16816(acc[2], ah[ks][0], ah[ks][1], ah[ks][2], ah[ks][3], h10, h11);
        MMA16816(acc[3], ah[ks][0], ah[ks][1], ah[ks][2], ah[ks][3], h12, h13);
        MMA16816(acc[0], al[ks][0], al[ks][1], al[ks][2], al[ks][3], h00, h01);
        MMA16816(acc[1], al[ks][0], al[ks][1], al[ks][2], al[ks][3], h02, h03);
        MMA16816(acc[2], al[ks][0], al[ks][1], al[ks][2], al[ks][3], h10, h11);
        MMA16816(acc[3], al[ks][0], al[ks][1], al[ks][2], al[ks][3], h12, h13);
        MMA16816(acc[0], ah[ks][0], ah[ks][1], ah[ks][2], ah[ks][3], l00, l01);
        MMA16816(acc[1], ah[ks][0], ah[ks][1], ah[ks][2], ah[ks][3], l02, l03);
        MMA16816(acc[2], ah[ks][0], ah[ks][1], ah[ks][2], ah[ks][3], l10, l11);
        MMA16816(acc[3], ah[ks][0], ah[ks][1], ah[ks][2], ah[ks][3], l12, l13);
    }
}

// one hidden layer: in-frags -> out-frags, group-interleaved epilogue
__device__ __forceinline__ void layer_mid(const u32 ah[8][4], const u32 al[8][4],
                                          u32 wh, u32 wl, const float* __restrict__ bias,
                                          int qc, u32 oh[8][4], u32 ol[8][4]) {
#pragma unroll
    for (int g = 0; g < 4; ++g) {
        float acc[4][4];
#pragma unroll
        for (int q = 0; q < 4; ++q) {
            int j0 = (g * 4 + q) * 8 + qc;
            float bb0 = bias[j0], bb1 = bias[j0 + 1];
            acc[q][0] = bb0; acc[q][1] = bb1; acc[q][2] = bb0; acc[q][3] = bb1;
        }
        group_mma(ah, al, wh, wl, g, acc);
        // epilogue for this group: tanh + split into out frags ks2 = 2g, 2g+1
#pragma unroll
        for (int q = 0; q < 4; ++q) {
            int nQ = g * 4 + q;
            float v0 = tanh_nc(acc[q][0]);
            float v1 = tanh_nc(acc[q][1]);
            float v2 = tanh_nc(acc[q][2]);
            float v3 = tanh_nc(acc[q][3]);
            int ks2 = nQ >> 1, o = (nQ & 1) * 2;
            split_pair(v0, v1, oh[ks2][o],     ol[ks2][o]);
            split_pair(v2, v3, oh[ks2][o + 1], ol[ks2][o + 1]);
        }
    }
}

__global__ __launch_bounds__(NTHREADS, 1)
void mlp_hmma4(const float* __restrict__ X,  const float* __restrict__ Y,
               const float* __restrict__ C1, const float* __restrict__ C2,
               const float* __restrict__ W1, const float* __restrict__ b1,
               const float* __restrict__ W2, const float* __restrict__ b2,
               const float* __restrict__ W3, const float* __restrict__ b3,
               const float* __restrict__ W4, const float* __restrict__ b4,
               float* __restrict__ out, int npts) {
    extern __shared__ __align__(128) char sm[];
    const u32 smB = smem_u32(sm);
    const int t = threadIdx.x, w = t >> 5, lane = t & 31;

    float* sW1f = (float*)(sm + SW1_O);
    float* sB1f = (float*)(sm + SB1_O);
    float* sB2f = (float*)(sm + SB2_O);
    float* sB3f = (float*)(sm + SB3_O);
    float* sW4f = (float*)(sm + SW4_O);

    // ---- one-time staging ----
    for (int i = t; i < 512; i += NTHREADS) sW1f[i] = W1[i];
    if (t < 128) { sB1f[t] = b1[t]; sB2f[t] = b2[t]; sB3f[t] = b3[t]; }
    if (t < 256) sW4f[t] = W4[t];
    stage_weights(sm, W2H, W2L, W2, t);
    stage_weights(sm, W3H, W3L, W3, t);
    const float b40 = b4[0], b41 = b4[1];
    __syncthreads();

    const int qr = lane >> 2;           // fragment row within stripe
    const int qc = (lane & 3) * 2;      // fragment col pair base
    const u32 offB = (u32)(((lane & 7) + ((lane >> 4) & 1) * 8) * RPITCH
                           + ((lane >> 3) & 1) * 16);
    const u32 w2h = smB + W2H + offB, w2l = smB + W2L + offB;
    const u32 w3h = smB + W3H + offB, w3l = smB + W3L + offB;

    const int n16 = (npts + 15) >> 4;                 // 16-point micro-tiles
    const int gw  = blockIdx.x * NWARPS + w;
    const int nw  = gridDim.x * NWARPS;

    for (int wt = gw; wt < n16; wt += nw) {
        const int r0 = wt * 16 + qr, r1 = r0 + 8;
        const bool ok0 = r0 < npts, ok1 = r1 < npts;
        const float x0 = ok0 ? X[r0] : 0.f, y0 = ok0 ? Y[r0] : 0.f;
        const float p0 = ok0 ? C1[r0] : 0.f, q0 = ok0 ? C2[r0] : 0.f;
        const float x1 = ok1 ? X[r1] : 0.f, y1 = ok1 ? Y[r1] : 0.f;
        const float p1 = ok1 ? C1[r1] : 0.f, q1 = ok1 ? C2[r1] : 0.f;

        u32 fa_h[8][4], fa_l[8][4];     // layer-1 output frags
        u32 fb_h[8][4], fb_l[8][4];     // layer-2 output frags

        // ---- layer 1: compute directly in A-fragment pattern ----
#pragma unroll
        for (int nt = 0; nt < 16; ++nt) {
            const int j0 = nt * 8 + qc;
            const float wa0 = sW1f[j0],           wb0 = sW1f[HID + j0];
            const float wc0 = sW1f[2 * HID + j0], wd0 = sW1f[3 * HID + j0];
            const float wa1 = sW1f[j0 + 1],           wb1 = sW1f[HID + j0 + 1];
            const float wc1 = sW1f[2 * HID + j0 + 1], wd1 = sW1f[3 * HID + j0 + 1];
            const float bb0 = sB1f[j0], bb1 = sB1f[j0 + 1];

            float v0 = fmaf(q0, wd0, fmaf(p0, wc0, fmaf(y0, wb0, fmaf(x0, wa0, bb0))));
            float v1 = fmaf(q0, wd1, fmaf(p0, wc1, fmaf(y0, wb1, fmaf(x0, wa1, bb1))));
            float v2 = fmaf(q1, wd0, fmaf(p1, wc0, fmaf(y1, wb0, fmaf(x1, wa0, bb0))));
            float v3 = fmaf(q1, wd1, fmaf(p1, wc1, fmaf(y1, wb1, fmaf(x1, wa1, bb1))));
            v0 = tanh_nc(v0); v1 = tanh_nc(v1); v2 = tanh_nc(v2); v3 = tanh_nc(v3);

            const int ks = nt >> 1, o = (nt & 1) * 2;
            split_pair(v0, v1, fa_h[ks][o],     fa_l[ks][o]);
            split_pair(v2, v3, fa_h[ks][o + 1], fa_l[ks][o + 1]);
        }

        // ---- layer 2: group-interleaved HMMA + epilogue ----
        layer_mid(fa_h, fa_l, w2h, w2l, sB2f, qc, fb_h, fb_l);

        // ---- layer 3 + fused layer-4 dot, group-interleaved ----
        float s00 = 0.f, s01 = 0.f, s10 = 0.f, s11 = 0.f;
#pragma unroll
        for (int g = 0; g < 4; ++g) {
            float acc[4][4];
#pragma unroll
            for (int q = 0; q < 4; ++q) {
                int j0 = (g * 4 + q) * 8 + qc;
                float bb0 = sB3f[j0], bb1 = sB3f[j0 + 1];
                acc[q][0] = bb0; acc[q][1] = bb1; acc[q][2] = bb0; acc[q][3] = bb1;
            }
            group_mma(fb_h, fb_l, w3h, w3l, g, acc);
#pragma unroll
            for (int q = 0; q < 4; ++q) {
                int j0 = (g * 4 + q) * 8 + qc;
                float h0 = tanh_nc(acc[q][0]);
                float h1 = tanh_nc(acc[q][1]);
                float h2 = tanh_nc(acc[q][2]);
                float h3 = tanh_nc(acc[q][3]);
                float2 u0 = *(const float2*)(sW4f + 2 * j0);
                float2 u1 = *(const float2*)(sW4f + 2 * j0 + 2);
                s00 = fmaf(h0, u0.x, s00); s01 = fmaf(h0, u0.y, s01);
                s00 = fmaf(h1, u1.x, s00); s01 = fmaf(h1, u1.y, s01);
                s10 = fmaf(h2, u0.x, s10); s11 = fmaf(h2, u0.y, s11);
                s10 = fmaf(h3, u1.x, s10); s11 = fmaf(h3, u1.y, s11);
            }
        }
        // reduce across the 4 lanes of each row group and store
#pragma unroll
        for (int d = 1; d <= 2; d <<= 1) {
            s00 += __shfl_xor_sync(0xFFFFFFFFu, s00, d);
            s01 += __shfl_xor_sync(0xFFFFFFFFu, s01, d);
            s10 += __shfl_xor_sync(0xFFFFFFFFu, s10, d);
            s11 += __shfl_xor_sync(0xFFFFFFFFu, s11, d);
        }
        if ((lane & 3) == 0) {
            if (ok0) *(float2*)(out + 2 * (size_t)r0) = make_float2(b40 + s00, b41 + s01);
            if (ok1) *(float2*)(out + 2 * (size_t)r1) = make_float2(b40 + s10, b41 + s11);
        }
    }
}

extern "C" void kernel_launch(void* const* d_in, const int* in_sizes, int n_in,
                              void* d_out, int out_size) {
    const float* x  = (const float*)d_in[0];
    const float* y  = (const float*)d_in[1];
    const float* c1 = (const float*)d_in[2];
    const float* c2 = (const float*)d_in[3];
    const float* W1 = (const float*)d_in[4];
    const float* b1 = (const float*)d_in[5];
    const float* W2 = (const float*)d_in[6];
    const float* b2 = (const float*)d_in[7];
    const float* W3 = (const float*)d_in[8];
    const float* b3 = (const float*)d_in[9];
    const float* W4 = (const float*)d_in[10];
    const float* b4 = (const float*)d_in[11];
    float* out = (float*)d_out;

    const int npts = in_sizes[0];

    int dev = 0, sms = 148;
    cudaGetDevice(&dev);
    cudaDeviceGetAttribute(&sms, cudaDevAttrMultiProcessorCount, dev);
    int n16 = (npts + 15) / 16;
    int maxCtas = (n16 + NWARPS - 1) / NWARPS;
    int grid = sms < maxCtas ? sms : maxCtas;

    cudaFuncSetAttribute(mlp_hmma4, cudaFuncAttributeMaxDynamicSharedMemorySize, SMEM_BYTES);
    mlp_hmma4<<<grid, NTHREADS, SMEM_BYTES>>>(x, y, c1, c2, W1, b1, W2, b2, W3, b3, W4, b4,
                                              out, npts);
}

// round 13
// speedup vs baseline: 5.8474x; 1.3329x over previous
#include <cuda_runtime.h>
#include <cstdint>

// MLP [N,4]->128->128->128->2, tanh; N=524288.
// R11: fp16 HMMA 2-product split (Ah*Wh + Al*Wh = A*Wh exactly in A; the only
// error is weight fp16 quantization ~2^-12, end-to-end ~5e-4 < 1e-3 gate).
// 1/3 fewer MMAs + half the LDSM/weight-smem vs the bf16 3-product scheme.
// Register-resident A fragments, group-interleaved epilogue, warp-autonomous
// 16-point micro-tiles, weights staged to smem once per CTA.

#define HID 128
#define NTHREADS 384
#define NWARPS 12
#define RPITCH 272u            // weight tile row pitch (bytes); conflict-free ldmatrix

// smem byte offsets
#define W2H    0u              // W^T tiles [j][k] fp16 (hi only), 128 rows x 272B
#define W3H    34816u
#define SW1_O  69632u          // 512 f
#define SB1_O  71680u          // 128 f
#define SB2_O  72192u
#define SB3_O  72704u
#define SW4_O  73216u          // 256 f
#define SMEM_BYTES 74240u

typedef uint32_t u32;

__device__ __forceinline__ u32 smem_u32(const void* p) {
    u32 a;
    asm("{ .reg .u64 t; cvta.to.shared.u64 t, %1; cvt.u32.u64 %0, t; }" : "=r"(a) : "l"(p));
    return a;
}

#define LDSM4(r0, r1, r2, r3, addr) \
    asm volatile("ldmatrix.sync.aligned.m8n8.x4.shared.b16 {%0,%1,%2,%3}, [%4];" \
                 : "=r"(r0), "=r"(r1), "=r"(r2), "=r"(r3) : "r"(addr))

#define MMA16816(d, a0, a1, a2, a3, b0, b1) \
    asm volatile("mma.sync.aligned.m16n8k16.row.col.f32.f16.f16.f32 " \
                 "{%0,%1,%2,%3}, {%4,%5,%6,%7}, {%8,%9}, {%0,%1,%2,%3};" \
                 : "+f"((d)[0]), "+f"((d)[1]), "+f"((d)[2]), "+f"((d)[3]) \
                 : "r"(a0), "r"(a1), "r"(a2), "r"(a3), "r"(b0), "r"(b1))

// clamp-free: 1 - 2/(e^{2v}+1); e=inf -> 1, e=0 -> -1, both exact.
__device__ __forceinline__ float tanh_nc(float v) {
    float e = __expf(2.0f * v);
    return 1.0f - __fdividef(2.0f, e + 1.0f);
}

// fp32 pair -> (hi = rn fp16x2, lo = rn fp16x2 of exact residual); v0 -> low half.
// hi + lo == v to ~2^-23 relative, so A-side split error is negligible.
__device__ __forceinline__ void split_pair(float v0, float v1, u32& hp, u32& lp) {
    asm("cvt.rn.f16x2.f32 %0, %1, %2;" : "=r"(hp) : "f"(v1), "f"(v0));
    float h0, h1;
    asm("{\n\t.reg .b16 a, b;\n\tmov.b32 {a, b}, %2;\n\t"
        "cvt.f32.f16 %0, a;\n\tcvt.f32.f16 %1, b;\n\t}"
        : "=f"(h0), "=f"(h1) : "r"(hp));
    asm("cvt.rn.f16x2.f32 %0, %1, %2;" : "=r"(lp) : "f"(v1 - h1), "f"(v0 - h0));
}

// stage W[k][j] (128x128 f32, j contiguous) -> transposed fp16 tiles [j][k] (rn)
__device__ __forceinline__ void stage_weights(char* sm, u32 hiOff,
                                              const float* __restrict__ Wg, int t) {
    for (int idx = t; idx < 64 * 128; idx += NTHREADS) {
        int j = idx & 127, k = (idx >> 7) << 1;
        float w0 = Wg[k * HID + j], w1 = Wg[(k + 1) * HID + j];
        u32 hp;
        asm("cvt.rn.f16x2.f32 %0, %1, %2;" : "=r"(hp) : "f"(w1), "f"(w0));
        *(u32*)(sm + hiOff + (u32)j * RPITCH + (u32)k * 2u) = hp;
    }
}

// 128 MMAs for one n32 group (n16 blocks 2g, 2g+1) of one layer.
// 4 accumulator quads, round-robin order (dep distance 4 issue slots).
__device__ __forceinline__ void group_mma(const u32 ah[8][4], const u32 al[8][4],
                                          u32 wh, int g, float acc[4][4]) {
#pragma unroll
    for (int ks = 0; ks < 8; ++ks) {
        const u32 o0 = (u32)(2 * g)     * 4352u + (u32)ks * 32u;
        const u32 o1 = (u32)(2 * g + 1) * 4352u + (u32)ks * 32u;
        u32 h00, h01, h02, h03, h10, h11, h12, h13;
        LDSM4(h00, h01, h02, h03, wh + o0);
        LDSM4(h10, h11, h12, h13, wh + o1);
        MMA16816(acc[0], ah[ks][0], ah[ks][1], ah[ks][2], ah[ks][3], h00, h01);
        MMA16816(acc[1], ah[ks][0], ah[ks][1], ah[ks][2], ah[ks][3], h02, h03);
        MMA16816(acc[2], ah[ks][0], ah[ks][1], ah[ks][2], ah[ks][3], h10, h11);
        MMA16816(acc[3], ah[ks][0], ah[ks][1], ah[ks][2], ah[ks][3], h12, h13);
        MMA16816(acc[0], al[ks][0], al[ks][1], al[ks][2], al[ks][3], h00, h01);
        MMA16816(acc[1], al[ks][0], al[ks][1], al[ks][2], al[ks][3], h02, h03);
        MMA16816(acc[2], al[ks][0], al[ks][1], al[ks][2], al[ks][3], h10, h11);
        MMA16816(acc[3], al[ks][0], al[ks][1], al[ks][2], al[ks][3], h12, h13);
    }
}

// one hidden layer: in-frags -> out-frags, group-interleaved epilogue
__device__ __forceinline__ void layer_mid(const u32 ah[8][4], const u32 al[8][4],
                                          u32 wh, const float* __restrict__ bias,
                                          int qc, u32 oh[8][4], u32 ol[8][4]) {
#pragma unroll
    for (int g = 0; g < 4; ++g) {
        float acc[4][4];
#pragma unroll
        for (int q = 0; q < 4; ++q) {
            int j0 = (g * 4 + q) * 8 + qc;
            float bb0 = bias[j0], bb1 = bias[j0 + 1];
            acc[q][0] = bb0; acc[q][1] = bb1; acc[q][2] = bb0; acc[q][3] = bb1;
        }
        group_mma(ah, al, wh, g, acc);
#pragma unroll
        for (int q = 0; q < 4; ++q) {
            int nQ = g * 4 + q;
            float v0 = tanh_nc(acc[q][0]);
            float v1 = tanh_nc(acc[q][1]);
            float v2 = tanh_nc(acc[q][2]);
            float v3 = tanh_nc(acc[q][3]);
            int ks2 = nQ >> 1, o = (nQ & 1) * 2;
            split_pair(v0, v1, oh[ks2][o],     ol[ks2][o]);
            split_pair(v2, v3, oh[ks2][o + 1], ol[ks2][o + 1]);
        }
    }
}

__global__ __launch_bounds__(NTHREADS, 1)
void mlp_hmma5(const float* __restrict__ X,  const float* __restrict__ Y,
               const float* __restrict__ C1, const float* __restrict__ C2,
               const float* __restrict__ W1, const float* __restrict__ b1,
               const float* __restrict__ W2, const float* __restrict__ b2,
               const float* __restrict__ W3, const float* __restrict__ b3,
               const float* __restrict__ W4, const float* __restrict__ b4,
               float* __restrict__ out, int npts) {
    extern __shared__ __align__(128) char sm[];
    const u32 smB = smem_u32(sm);
    const int t = threadIdx.x, w = t >> 5, lane = t & 31;

    float* sW1f = (float*)(sm + SW1_O);
    float* sB1f = (float*)(sm + SB1_O);
    float* sB2f = (float*)(sm + SB2_O);
    float* sB3f = (float*)(sm + SB3_O);
    float* sW4f = (float*)(sm + SW4_O);

    // ---- one-time staging ----
    for (int i = t; i < 512; i += NTHREADS) sW1f[i] = W1[i];
    if (t < 128) { sB1f[t] = b1[t]; sB2f[t] = b2[t]; sB3f[t] = b3[t]; }
    if (t < 256) sW4f[t] = W4[t];
    stage_weights(sm, W2H, W2, t);
    stage_weights(sm, W3H, W3, t);
    const float b40 = b4[0], b41 = b4[1];
    __syncthreads();

    const int qr = lane >> 2;           // fragment row within stripe
    const int qc = (lane & 3) * 2;      // fragment col pair base
    const u32 offB = (u32)(((lane & 7) + ((lane >> 4) & 1) * 8) * RPITCH
                           + ((lane >> 3) & 1) * 16);
    const u32 w2h = smB + W2H + offB;
    const u32 w3h = smB + W3H + offB;

    const int n16 = (npts + 15) >> 4;                 // 16-point micro-tiles
    const int gw  = blockIdx.x * NWARPS + w;
    const int nw  = gridDim.x * NWARPS;

    for (int wt = gw; wt < n16; wt += nw) {
        const int r0 = wt * 16 + qr, r1 = r0 + 8;
        const bool ok0 = r0 < npts, ok1 = r1 < npts;
        const float x0 = ok0 ? X[r0] : 0.f, y0 = ok0 ? Y[r0] : 0.f;
        const float p0 = ok0 ? C1[r0] : 0.f, q0 = ok0 ? C2[r0] : 0.f;
        const float x1 = ok1 ? X[r1] : 0.f, y1 = ok1 ? Y[r1] : 0.f;
        const float p1 = ok1 ? C1[r1] : 0.f, q1 = ok1 ? C2[r1] : 0.f;

        u32 fa_h[8][4], fa_l[8][4];     // layer-1 output frags
        u32 fb_h[8][4], fb_l[8][4];     // layer-2 output frags

        // ---- layer 1: compute directly in A-fragment pattern ----
#pragma unroll
        for (int nt = 0; nt < 16; ++nt) {
            const int j0 = nt * 8 + qc;
            const float wa0 = sW1f[j0],           wb0 = sW1f[HID + j0];
            const float wc0 = sW1f[2 * HID + j0], wd0 = sW1f[3 * HID + j0];
            const float wa1 = sW1f[j0 + 1],           wb1 = sW1f[HID + j0 + 1];
            const float wc1 = sW1f[2 * HID + j0 + 1], wd1 = sW1f[3 * HID + j0 + 1];
            const float bb0 = sB1f[j0], bb1 = sB1f[j0 + 1];

            float v0 = fmaf(q0, wd0, fmaf(p0, wc0, fmaf(y0, wb0, fmaf(x0, wa0, bb0))));
            float v1 = fmaf(q0, wd1, fmaf(p0, wc1, fmaf(y0, wb1, fmaf(x0, wa1, bb1))));
            float v2 = fmaf(q1, wd0, fmaf(p1, wc0, fmaf(y1, wb0, fmaf(x1, wa0, bb0))));
            float v3 = fmaf(q1, wd1, fmaf(p1, wc1, fmaf(y1, wb1, fmaf(x1, wa1, bb1))));
            v0 = tanh_nc(v0); v1 = tanh_nc(v1); v2 = tanh_nc(v2); v3 = tanh_nc(v3);

            const int ks = nt >> 1, o = (nt & 1) * 2;
            split_pair(v0, v1, fa_h[ks][o],     fa_l[ks][o]);
            split_pair(v2, v3, fa_h[ks][o + 1], fa_l[ks][o + 1]);
        }

        // ---- layer 2: group-interleaved HMMA + epilogue ----
        layer_mid(fa_h, fa_l, w2h, sB2f, qc, fb_h, fb_l);

        // ---- layer 3 + fused layer-4 dot, group-interleaved ----
        float s00 = 0.f, s01 = 0.f, s10 = 0.f, s11 = 0.f;
#pragma unroll
        for (int g = 0; g < 4; ++g) {
            float acc[4][4];
#pragma unroll
            for (int q = 0; q < 4; ++q) {
                int j0 = (g * 4 + q) * 8 + qc;
                float bb0 = sB3f[j0], bb1 = sB3f[j0 + 1];
                acc[q][0] = bb0; acc[q][1] = bb1; acc[q][2] = bb0; acc[q][3] = bb1;
            }
            group_mma(fb_h, fb_l, w3h, g, acc);
#pragma unroll
            for (int q = 0; q < 4; ++q) {
                int j0 = (g * 4 + q) * 8 + qc;
                float h0 = tanh_nc(acc[q][0]);
                float h1 = tanh_nc(acc[q][1]);
                float h2 = tanh_nc(acc[q][2]);
                float h3 = tanh_nc(acc[q][3]);
                float2 u0 = *(const float2*)(sW4f + 2 * j0);
                float2 u1 = *(const float2*)(sW4f + 2 * j0 + 2);
                s00 = fmaf(h0, u0.x, s00); s01 = fmaf(h0, u0.y, s01);
                s00 = fmaf(h1, u1.x, s00); s01 = fmaf(h1, u1.y, s01);
                s10 = fmaf(h2, u0.x, s10); s11 = fmaf(h2, u0.y, s11);
                s10 = fmaf(h3, u1.x, s10); s11 = fmaf(h3, u1.y, s11);
            }
        }
        // reduce across the 4 lanes of each row group and store
#pragma unroll
        for (int d = 1; d <= 2; d <<= 1) {
            s00 += __shfl_xor_sync(0xFFFFFFFFu, s00, d);
            s01 += __shfl_xor_sync(0xFFFFFFFFu, s01, d);
            s10 += __shfl_xor_sync(0xFFFFFFFFu, s10, d);
            s11 += __shfl_xor_sync(0xFFFFFFFFu, s11, d);
        }
        if ((lane & 3) == 0) {
            if (ok0) *(float2*)(out + 2 * (size_t)r0) = make_float2(b40 + s00, b41 + s01);
            if (ok1) *(float2*)(out + 2 * (size_t)r1) = make_float2(b40 + s10, b41 + s11);
        }
    }
}

extern "C" void kernel_launch(void* const* d_in, const int* in_sizes, int n_in,
                              void* d_out, int out_size) {
    const float* x  = (const float*)d_in[0];
    const float* y  = (const float*)d_in[1];
    const float* c1 = (const float*)d_in[2];
    const float* c2 = (const float*)d_in[3];
    const float* W1 = (const float*)d_in[4];
    const float* b1 = (const float*)d_in[5];
    const float* W2 = (const float*)d_in[6];
    const float* b2 = (const float*)d_in[7];
    const float* W3 = (const float*)d_in[8];
    const float* b3 = (const float*)d_in[9];
    const float* W4 = (const float*)d_in[10];
    const float* b4 = (const float*)d_in[11];
    float* out = (float*)d_out;

    const int npts = in_sizes[0];

    int dev = 0, sms = 148;
    cudaGetDevice(&dev);
    cudaDeviceGetAttribute(&sms, cudaDevAttrMultiProcessorCount, dev);
    int n16 = (npts + 15) / 16;
    int maxCtas = (n16 + NWARPS - 1) / NWARPS;
    int grid = sms < maxCtas ? sms : maxCtas;

    cudaFuncSetAttribute(mlp_hmma5, cudaFuncAttributeMaxDynamicSharedMemorySize, SMEM_BYTES);
    mlp_hmma5<<<grid, NTHREADS, SMEM_BYTES>>>(x, y, c1, c2, W1, b1, W2, b2, W3, b3, W4, b4,
                                              out, npts);
}

// round 14
// speedup vs baseline: 8.0501x; 1.3767x over previous
#include <cuda_runtime.h>
#include <cstdint>

// MLP [N,4]->128->128->128->2, tanh; N=524288.
// R13: fp16 SINGLE-product HMMA (A and W both rn fp16; error = A-quant + W-quant
// ~ 3e-4 << 1e-3 gate). Halves MMAs and A-frag registers vs R11; freed registers
// spent on 16 warps/CTA (4/SMSP) for cross-warp pipe overlap.
// Register-resident A fragments, group-interleaved epilogue, warp-autonomous
// 16-point micro-tiles, weights staged to smem once per CTA.

#define HID 128
#define NTHREADS 512
#define NWARPS 16
#define RPITCH 272u            // weight tile row pitch (bytes); conflict-free ldmatrix

// smem byte offsets
#define W2H    0u              // W^T tiles [j][k] fp16, 128 rows x 272B
#define W3H    34816u
#define SW1_O  69632u          // 512 f
#define SB1_O  71680u          // 128 f
#define SB2_O  72192u
#define SB3_O  72704u
#define SW4_O  73216u          // 256 f
#define SMEM_BYTES 74240u

typedef uint32_t u32;

__device__ __forceinline__ u32 smem_u32(const void* p) {
    u32 a;
    asm("{ .reg .u64 t; cvta.to.shared.u64 t, %1; cvt.u32.u64 %0, t; }" : "=r"(a) : "l"(p));
    return a;
}

#define LDSM4(r0, r1, r2, r3, addr) \
    asm volatile("ldmatrix.sync.aligned.m8n8.x4.shared.b16 {%0,%1,%2,%3}, [%4];" \
                 : "=r"(r0), "=r"(r1), "=r"(r2), "=r"(r3) : "r"(addr))

#define MMA16816(d, a0, a1, a2, a3, b0, b1) \
    asm volatile("mma.sync.aligned.m16n8k16.row.col.f32.f16.f16.f32 " \
                 "{%0,%1,%2,%3}, {%4,%5,%6,%7}, {%8,%9}, {%0,%1,%2,%3};" \
                 : "+f"((d)[0]), "+f"((d)[1]), "+f"((d)[2]), "+f"((d)[3]) \
                 : "r"(a0), "r"(a1), "r"(a2), "r"(a3), "r"(b0), "r"(b1))

// clamp-free: 1 - 2/(e^{2v}+1); e=inf -> 1, e=0 -> -1, both exact.
__device__ __forceinline__ float tanh_nc(float v) {
    float e = __expf(2.0f * v);
    return 1.0f - __fdividef(2.0f, e + 1.0f);
}

// fp32 pair -> rn fp16x2; v0 -> low half (even column)
__device__ __forceinline__ u32 pack_f16(float v0, float v1) {
    u32 r;
    asm("cvt.rn.f16x2.f32 %0, %1, %2;" : "=r"(r) : "f"(v1), "f"(v0));
    return r;
}

// stage W[k][j] (128x128 f32, j contiguous) -> transposed fp16 tiles [j][k] (rn)
__device__ __forceinline__ void stage_weights(char* sm, u32 off,
                                              const float* __restrict__ Wg, int t) {
    for (int idx = t; idx < 64 * 128; idx += NTHREADS) {
        int j = idx & 127, k = (idx >> 7) << 1;
        float w0 = Wg[k * HID + j], w1 = Wg[(k + 1) * HID + j];
        *(u32*)(sm + off + (u32)j * RPITCH + (u32)k * 2u) = pack_f16(w0, w1);
    }
}

// 64 MMAs for one n32 group (n16 blocks 2g, 2g+1) of one layer.
// 4 accumulator quads, round-robin order (dep distance 4 issue slots).
__device__ __forceinline__ void group_mma(const u32 a[8][4], u32 wh, int g,
                                          float acc[4][4]) {
#pragma unroll
    for (int ks = 0; ks < 8; ++ks) {
        const u32 o0 = (u32)(2 * g)     * 4352u + (u32)ks * 32u;
        const u32 o1 = (u32)(2 * g + 1) * 4352u + (u32)ks * 32u;
        u32 h00, h01, h02, h03, h10, h11, h12, h13;
        LDSM4(h00, h01, h02, h03, wh + o0);
        LDSM4(h10, h11, h12, h13, wh + o1);
        MMA16816(acc[0], a[ks][0], a[ks][1], a[ks][2], a[ks][3], h00, h01);
        MMA16816(acc[1], a[ks][0], a[ks][1], a[ks][2], a[ks][3], h02, h03);
        MMA16816(acc[2], a[ks][0], a[ks][1], a[ks][2], a[ks][3], h10, h11);
        MMA16816(acc[3], a[ks][0], a[ks][1], a[ks][2], a[ks][3], h12, h13);
    }
}

// one hidden layer: in-frags -> out-frags, group-interleaved epilogue
__device__ __forceinline__ void layer_mid(const u32 a[8][4], u32 wh,
                                          const float* __restrict__ bias,
                                          int qc, u32 o[8][4]) {
#pragma unroll
    for (int g = 0; g < 4; ++g) {
        float acc[4][4];
#pragma unroll
        for (int q = 0; q < 4; ++q) {
            int j0 = (g * 4 + q) * 8 + qc;
            float bb0 = bias[j0], bb1 = bias[j0 + 1];
            acc[q][0] = bb0; acc[q][1] = bb1; acc[q][2] = bb0; acc[q][3] = bb1;
        }
        group_mma(a, wh, g, acc);
#pragma unroll
        for (int q = 0; q < 4; ++q) {
            int nQ = g * 4 + q;
            float v0 = tanh_nc(acc[q][0]);
            float v1 = tanh_nc(acc[q][1]);
            float v2 = tanh_nc(acc[q][2]);
            float v3 = tanh_nc(acc[q][3]);
            int ks2 = nQ >> 1, oo = (nQ & 1) * 2;
            o[ks2][oo]     = pack_f16(v0, v1);
            o[ks2][oo + 1] = pack_f16(v2, v3);
        }
    }
}

__global__ __launch_bounds__(NTHREADS, 1)
void mlp_hmma6(const float* __restrict__ X,  const float* __restrict__ Y,
               const float* __restrict__ C1, const float* __restrict__ C2,
               const float* __restrict__ W1, const float* __restrict__ b1,
               const float* __restrict__ W2, const float* __restrict__ b2,
               const float* __restrict__ W3, const float* __restrict__ b3,
               const float* __restrict__ W4, const float* __restrict__ b4,
               float* __restrict__ out, int npts) {
    extern __shared__ __align__(128) char sm[];
    const u32 smB = smem_u32(sm);
    const int t = threadIdx.x, w = t >> 5, lane = t & 31;

    float* sW1f = (float*)(sm + SW1_O);
    float* sB1f = (float*)(sm + SB1_O);
    float* sB2f = (float*)(sm + SB2_O);
    float* sB3f = (float*)(sm + SB3_O);
    float* sW4f = (float*)(sm + SW4_O);

    // ---- one-time staging ----
    for (int i = t; i < 512; i += NTHREADS) sW1f[i] = W1[i];
    if (t < 128) { sB1f[t] = b1[t]; sB2f[t] = b2[t]; sB3f[t] = b3[t]; }
    if (t < 256) sW4f[t] = W4[t];
    stage_weights(sm, W2H, W2, t);
    stage_weights(sm, W3H, W3, t);
    const float b40 = b4[0], b41 = b4[1];
    __syncthreads();

    const int qr = lane >> 2;           // fragment row within stripe
    const int qc = (lane & 3) * 2;      // fragment col pair base
    const u32 offB = (u32)(((lane & 7) + ((lane >> 4) & 1) * 8) * RPITCH
                           + ((lane >> 3) & 1) * 16);
    const u32 w2h = smB + W2H + offB;
    const u32 w3h = smB + W3H + offB;

    const int n16 = (npts + 15) >> 4;                 // 16-point micro-tiles
    const int gw  = blockIdx.x * NWARPS + w;
    const int nw  = gridDim.x * NWARPS;

    for (int wt = gw; wt < n16; wt += nw) {
        const int r0 = wt * 16 + qr, r1 = r0 + 8;
        const bool ok0 = r0 < npts, ok1 = r1 < npts;
        const float x0 = ok0 ? X[r0] : 0.f, y0 = ok0 ? Y[r0] : 0.f;
        const float p0 = ok0 ? C1[r0] : 0.f, q0 = ok0 ? C2[r0] : 0.f;
        const float x1 = ok1 ? X[r1] : 0.f, y1 = ok1 ? Y[r1] : 0.f;
        const float p1 = ok1 ? C1[r1] : 0.f, q1 = ok1 ? C2[r1] : 0.f;

        u32 fa[8][4];                   // layer-1 output frags (fp16x2)
        u32 fb[8][4];                   // layer-2 output frags

        // ---- layer 1: compute directly in A-fragment pattern ----
#pragma unroll
        for (int nt = 0; nt < 16; ++nt) {
            const int j0 = nt * 8 + qc;
            const float wa0 = sW1f[j0],           wb0 = sW1f[HID + j0];
            const float wc0 = sW1f[2 * HID + j0], wd0 = sW1f[3 * HID + j0];
            const float wa1 = sW1f[j0 + 1],           wb1 = sW1f[HID + j0 + 1];
            const float wc1 = sW1f[2 * HID + j0 + 1], wd1 = sW1f[3 * HID + j0 + 1];
            const float bb0 = sB1f[j0], bb1 = sB1f[j0 + 1];

            float v0 = fmaf(q0, wd0, fmaf(p0, wc0, fmaf(y0, wb0, fmaf(x0, wa0, bb0))));
            float v1 = fmaf(q0, wd1, fmaf(p0, wc1, fmaf(y0, wb1, fmaf(x0, wa1, bb1))));
            float v2 = fmaf(q1, wd0, fmaf(p1, wc0, fmaf(y1, wb0, fmaf(x1, wa0, bb0))));
            float v3 = fmaf(q1, wd1, fmaf(p1, wc1, fmaf(y1, wb1, fmaf(x1, wa1, bb1))));
            v0 = tanh_nc(v0); v1 = tanh_nc(v1); v2 = tanh_nc(v2); v3 = tanh_nc(v3);

            const int ks = nt >> 1, o = (nt & 1) * 2;
            fa[ks][o]     = pack_f16(v0, v1);
            fa[ks][o + 1] = pack_f16(v2, v3);
        }

        // ---- layer 2: group-interleaved HMMA + epilogue ----
        layer_mid(fa, w2h, sB2f, qc, fb);

        // ---- layer 3 + fused layer-4 dot, group-interleaved ----
        float s00 = 0.f, s01 = 0.f, s10 = 0.f, s11 = 0.f;
#pragma unroll
        for (int g = 0; g < 4; ++g) {
            float acc[4][4];
#pragma unroll
            for (int q = 0; q < 4; ++q) {
                int j0 = (g * 4 + q) * 8 + qc;
                float bb0 = sB3f[j0], bb1 = sB3f[j0 + 1];
                acc[q][0] = bb0; acc[q][1] = bb1; acc[q][2] = bb0; acc[q][3] = bb1;
            }
            group_mma(fb, w3h, g, acc);
#pragma unroll
            for (int q = 0; q < 4; ++q) {
                int j0 = (g * 4 + q) * 8 + qc;
                float h0 = tanh_nc(acc[q][0]);
                float h1 = tanh_nc(acc[q][1]);
                float h2 = tanh_nc(acc[q][2]);
                float h3 = tanh_nc(acc[q][3]);
                float2 u0 = *(const float2*)(sW4f + 2 * j0);
                float2 u1 = *(const float2*)(sW4f + 2 * j0 + 2);
                s00 = fmaf(h0, u0.x, s00); s01 = fmaf(h0, u0.y, s01);
                s00 = fmaf(h1, u1.x, s00); s01 = fmaf(h1, u1.y, s01);
                s10 = fmaf(h2, u0.x, s10); s11 = fmaf(h2, u0.y, s11);
                s10 = fmaf(h3, u1.x, s10); s11 = fmaf(h3, u1.y, s11);
            }
        }
        // reduce across the 4 lanes of each row group and store
#pragma unroll
        for (int d = 1; d <= 2; d <<= 1) {
            s00 += __shfl_xor_sync(0xFFFFFFFFu, s00, d);
            s01 += __shfl_xor_sync(0xFFFFFFFFu, s01, d);
            s10 += __shfl_xor_sync(0xFFFFFFFFu, s10, d);
            s11 += __shfl_xor_sync(0xFFFFFFFFu, s11, d);
        }
        if ((lane & 3) == 0) {
            if (ok0) *(float2*)(out + 2 * (size_t)r0) = make_float2(b40 + s00, b41 + s01);
            if (ok1) *(float2*)(out + 2 * (size_t)r1) = make_float2(b40 + s10, b41 + s11);
        }
    }
}

extern "C" void kernel_launch(void* const* d_in, const int* in_sizes, int n_in,
                              void* d_out, int out_size) {
    const float* x  = (const float*)d_in[0];
    const float* y  = (const float*)d_in[1];
    const float* c1 = (const float*)d_in[2];
    const float* c2 = (const float*)d_in[3];
    const float* W1 = (const float*)d_in[4];
    const float* b1 = (const float*)d_in[5];
    const float* W2 = (const float*)d_in[6];
    const float* b2 = (const float*)d_in[7];
    const float* W3 = (const float*)d_in[8];
    const float* b3 = (const float*)d_in[9];
    const float* W4 = (const float*)d_in[10];
    const float* b4 = (const float*)d_in[11];
    float* out = (float*)d_out;

    const int npts = in_sizes[0];

    int dev = 0, sms = 148;
    cudaGetDevice(&dev);
    cudaDeviceGetAttribute(&sms, cudaDevAttrMultiProcessorCount, dev);
    int n16 = (npts + 15) / 16;
    int maxCtas = (n16 + NWARPS - 1) / NWARPS;
    int grid = sms < maxCtas ? sms : maxCtas;

    cudaFuncSetAttribute(mlp_hmma6, cudaFuncAttributeMaxDynamicSharedMemorySize, SMEM_BYTES);
    mlp_hmma6<<<grid, NTHREADS, SMEM_BYTES>>>(x, y, c1, c2, W1, b1, W2, b2, W3, b3, W4, b4,
                                              out, npts);
}